// round 3
// baseline (speedup 1.0000x reference)
#include <cuda_runtime.h>
#include <cstdint>

// Problem constants: B=C=P=D=256
#define N256 256
#define EPS 1e-5f

// ---------------- scratch (device globals; no allocations allowed) ----------
__device__ float g_mask[256 * 256];         // [P,C] softmax mask, tf32-rounded
__device__ float g_xprompt[256 * 256];      // [P,D]
__device__ float g_xcol[256 * 256];         // [C,D] LN(emb_column)
__device__ float g_xpin[256 * 512];         // [P,2D] concat(LN(emb_prompt), prev)
__device__ float g_logits[256 * 256];       // [P,C]

// ---------------- helpers ----------------------------------------------------
__device__ __forceinline__ float to_tf32(float x) {
    uint32_t u;
    asm("cvt.rna.tf32.f32 %0, %1;" : "=r"(u) : "f"(x));
    return __uint_as_float(u);
}

__device__ __forceinline__ float block_sum256(float v, float* s) {
    int t = threadIdx.x;
    s[t] = v; __syncthreads();
    for (int off = 128; off > 0; off >>= 1) {
        if (t < off) s[t] += s[t + off];
        __syncthreads();
    }
    float r = s[0]; __syncthreads();
    return r;
}

__device__ __forceinline__ float block_max256(float v, float* s) {
    int t = threadIdx.x;
    s[t] = v; __syncthreads();
    for (int off = 128; off > 0; off >>= 1) {
        if (t < off) s[t] = fmaxf(s[t], s[t + off]);
        __syncthreads();
    }
    float r = s[0]; __syncthreads();
    return r;
}

__device__ __forceinline__ void cp_async16(void* smem, const void* gmem) {
    uint32_t s = (uint32_t)__cvta_generic_to_shared(smem);
    asm volatile("cp.async.cg.shared.global [%0], [%1], 16;\n" :: "r"(s), "l"(gmem));
}
__device__ __forceinline__ void cp_commit() {
    asm volatile("cp.async.commit_group;\n" ::: "memory");
}
template <int N>
__device__ __forceinline__ void cp_wait() {
    asm volatile("cp.async.wait_group %0;\n" :: "n"(N) : "memory");
}

// ---------------- K1: prep — xpin rows (blocks 0..255), xcol rows (256..511) -
__global__ void prep_kernel(const float* __restrict__ embp,
                            const float* __restrict__ lnpw,
                            const float* __restrict__ lnpb,
                            const float* __restrict__ prev,
                            const float* __restrict__ embc,
                            const float* __restrict__ lncw,
                            const float* __restrict__ lncb) {
    __shared__ float s[256];
    int d = threadIdx.x;
    if (blockIdx.x < 256) {
        int p = blockIdx.x;
        float v = embp[p * N256 + d];
        float mu = block_sum256(v, s) * (1.0f / 256.0f);
        float var = block_sum256(v * v, s) * (1.0f / 256.0f) - mu * mu;
        float rstd = rsqrtf(var + EPS);
        g_xpin[p * 512 + d] = (v - mu) * rstd * lnpw[d] + lnpb[d];
        g_xpin[p * 512 + 256 + d] = prev[p * N256 + d];
    } else {
        int c = blockIdx.x - 256;
        float v = embc[c * N256 + d];
        float mu = block_sum256(v, s) * (1.0f / 256.0f);
        float var = block_sum256(v * v, s) * (1.0f / 256.0f) - mu * mu;
        float rstd = rsqrtf(var + EPS);
        g_xcol[c * N256 + d] = (v - mu) * rstd * lncw[d] + lncb[d];
    }
}

// ---------------- K2: x_prompt = xp_in @ W^T + b + emb_prompt ---------------
// M=256(p) x N=256(d) x K=512, 32x32 tiles, 2x2 per thread.
__global__ void xprompt_kernel(const float* __restrict__ W,
                               const float* __restrict__ bias,
                               const float* __restrict__ embp) {
    __shared__ float As[32][17];
    __shared__ float Ws[32][17];
    int tx = threadIdx.x, ty = threadIdx.y;
    int t = ty * 16 + tx;
    int p0 = blockIdx.y * 32;
    int d0 = blockIdx.x * 32;
    float acc[2][2] = {{0.f, 0.f}, {0.f, 0.f}};
    for (int kt = 0; kt < 32; kt++) {
        int k0 = kt * 16;
#pragma unroll
        for (int i = 0; i < 2; i++) {
            int idx = i * 256 + t;
            int r = idx >> 4, k = idx & 15;
            As[r][k] = g_xpin[(p0 + r) * 512 + k0 + k];
            Ws[r][k] = W[(d0 + r) * 512 + k0 + k];
        }
        __syncthreads();
#pragma unroll
        for (int kk = 0; kk < 16; kk++) {
            float a0 = As[ty * 2][kk], a1 = As[ty * 2 + 1][kk];
            float b0 = Ws[tx * 2][kk], b1 = Ws[tx * 2 + 1][kk];
            acc[0][0] += a0 * b0; acc[0][1] += a0 * b1;
            acc[1][0] += a1 * b0; acc[1][1] += a1 * b1;
        }
        __syncthreads();
    }
#pragma unroll
    for (int i = 0; i < 2; i++)
#pragma unroll
        for (int j = 0; j < 2; j++) {
            int p = p0 + ty * 2 + i, dd = d0 + tx * 2 + j;
            g_xprompt[p * N256 + dd] = acc[i][j] + bias[dd] + embp[p * N256 + dd];
        }
}

// ---------------- K3: logits = x_prompt @ x_col^T (32x32 tiles, 2x2/thread) -
__global__ void logits_kernel() {
    __shared__ float As[32][17];
    __shared__ float Bs[32][17];
    int tx = threadIdx.x, ty = threadIdx.y;
    int t = ty * 16 + tx;
    int p0 = blockIdx.y * 32;
    int c0 = blockIdx.x * 32;
    float acc[2][2] = {{0.f, 0.f}, {0.f, 0.f}};
    for (int kt = 0; kt < 16; kt++) {
        int k0 = kt * 16;
#pragma unroll
        for (int i = 0; i < 2; i++) {
            int idx = i * 256 + t;
            int r = idx >> 4, k = idx & 15;
            As[r][k] = g_xprompt[(p0 + r) * N256 + k0 + k];
            Bs[r][k] = g_xcol[(c0 + r) * N256 + k0 + k];
        }
        __syncthreads();
#pragma unroll
        for (int kk = 0; kk < 16; kk++) {
            float a0 = As[ty * 2][kk], a1 = As[ty * 2 + 1][kk];
            float b0 = Bs[tx * 2][kk], b1 = Bs[tx * 2 + 1][kk];
            acc[0][0] += a0 * b0; acc[0][1] += a0 * b1;
            acc[1][0] += a1 * b0; acc[1][1] += a1 * b1;
        }
        __syncthreads();
    }
#pragma unroll
    for (int i = 0; i < 2; i++)
#pragma unroll
        for (int j = 0; j < 2; j++)
            g_logits[(p0 + ty * 2 + i) * N256 + c0 + tx * 2 + j] = acc[i][j];
}

// ---------------- K4: row softmax (coalesced), tf32-rounded -----------------
__global__ void softmax_kernel() {
    __shared__ float s[256];
    int p = blockIdx.x, c = threadIdx.x;
    float v = g_logits[p * N256 + c];
    float mx = block_max256(v, s);
    float e = expf(v - mx);
    float sum = block_sum256(e, s);
    g_mask[p * N256 + c] = to_tf32(e / sum);
}

// ---------------- K5: fused out = mask @ LN(relu(feb + x*few)) --------------
// out[0,b,p,d] = (1+ew[p]) * sum_c mask[p,c]*xemb[b,c,d] + mask[b,p]*eb[b]
// Grid (m-tiles=2, b=256). Block tile 128(m) x 256(n), K=256 in chunks of 16.
// The xemb B-tile is computed on the fly (LN over full d possible since the
// block covers all 256 columns). mask tile streamed via double-buffered cp.async.
__device__ __forceinline__ void mma_tf32(float c[4],
                                         uint32_t a0, uint32_t a1, uint32_t a2, uint32_t a3,
                                         uint32_t b0, uint32_t b1) {
    asm volatile(
        "mma.sync.aligned.m16n8k8.row.col.f32.tf32.tf32.f32 "
        "{%0,%1,%2,%3}, {%4,%5,%6,%7}, {%8,%9}, {%0,%1,%2,%3};"
        : "+f"(c[0]), "+f"(c[1]), "+f"(c[2]), "+f"(c[3])
        : "r"(a0), "r"(a1), "r"(a2), "r"(a3), "r"(b0), "r"(b1));
}

#define AS_STRIDE 20    // 16 + 4 pad
#define BS_STRIDE 264   // 256 + 8 pad (264 mod 32 = 8 -> B-frag reads conflict-free)

__global__ __launch_bounds__(256) void out_gemm_fused(
    const float* __restrict__ x,
    const float* __restrict__ few,
    const float* __restrict__ feb,
    const float* __restrict__ lnew,
    const float* __restrict__ lneb,
    const float* __restrict__ ew,
    const float* __restrict__ eb,
    float* __restrict__ out) {
    __shared__ __align__(16) float As[2][128 * AS_STRIDE];
    __shared__ __align__(16) float Bs[16 * BS_STRIDE];
    __shared__ float sx[256];
    __shared__ float slnw[256];
    __shared__ float slnb[256];

    int m0 = blockIdx.x * 128;
    int b = blockIdx.y;
    const float* A = g_mask;     // [P=256, C=256]

    int tid = threadIdx.x;
    int lane = tid & 31;
    int warp = tid >> 5;
    int wm = (warp & 1) * 64;          // 2 warps along m
    int wn = (warp >> 1) * 64;         // 4 warps along n
    int grp = lane >> 2;               // 0..7
    int tig = lane & 3;                // 0..3

    sx[tid] = x[b * 256 + tid];
    slnw[tid] = lnew[tid];
    slnb[tid] = lneb[tid];

    // B-compute coordinates: row r (c within chunk), 16-col segment seg
    int r = tid >> 4;       // 0..15
    int seg = tid & 15;     // 0..15

    auto load_A = [&](int buf, int kt) {
        int k0 = kt * 16;
#pragma unroll
        for (int t = 0; t < 2; t++) {
            int idx = t * 256 + tid;
            int rr = idx >> 2;
            int kc = (idx & 3) << 2;
            cp_async16(&As[buf][rr * AS_STRIDE + kc],
                       A + (m0 + rr) * 256 + k0 + kc);
        }
        cp_commit();
    };

    float acc[4][8][4];
#pragma unroll
    for (int i = 0; i < 4; i++)
#pragma unroll
        for (int j = 0; j < 8; j++)
#pragma unroll
            for (int k = 0; k < 4; k++) acc[i][j][k] = 0.0f;

    load_A(0, 0);
    __syncthreads();   // sx/slnw/slnb visible

    for (int kt = 0; kt < 16; kt++) {
        int buf = kt & 1;

        // ---- compute xemb B-tile values for this chunk into registers ----
        int c = kt * 16 + r;
        float xv = sx[c];
        const float4* fw4 = (const float4*)(few + c * 256 + seg * 16);
        const float4* fb4 = (const float4*)(feb + c * 256 + seg * 16);
        float tv[16];
        float sum = 0.0f, sq = 0.0f;
#pragma unroll
        for (int q = 0; q < 4; q++) {
            float4 w4 = fw4[q];
            float4 b4 = fb4[q];
            float t0 = fmaxf(fmaf(xv, w4.x, b4.x), 0.0f);
            float t1 = fmaxf(fmaf(xv, w4.y, b4.y), 0.0f);
            float t2 = fmaxf(fmaf(xv, w4.z, b4.z), 0.0f);
            float t3 = fmaxf(fmaf(xv, w4.w, b4.w), 0.0f);
            tv[q * 4 + 0] = t0; tv[q * 4 + 1] = t1;
            tv[q * 4 + 2] = t2; tv[q * 4 + 3] = t3;
            sum += t0 + t1 + t2 + t3;
            sq = fmaf(t0, t0, sq); sq = fmaf(t1, t1, sq);
            sq = fmaf(t2, t2, sq); sq = fmaf(t3, t3, sq);
        }
        // reduce across the 16 threads sharing this row (lanes form 16-groups)
#pragma unroll
        for (int off = 8; off > 0; off >>= 1) {
            sum += __shfl_xor_sync(0xffffffff, sum, off, 16);
            sq  += __shfl_xor_sync(0xffffffff, sq, off, 16);
        }
        float mu = sum * (1.0f / 256.0f);
        float var = sq * (1.0f / 256.0f) - mu * mu;
        float rstd = rsqrtf(var + EPS);

        __syncthreads();   // all warps done with MMA(kt-1): Bs and As[buf^1] free
        if (kt < 15) load_A(buf ^ 1, kt + 1);

        // write LN'd tf32 values to Bs (float4 stores)
#pragma unroll
        for (int q = 0; q < 4; q++) {
            int d0 = seg * 16 + q * 4;
            float4 o;
            o.x = to_tf32((tv[q * 4 + 0] - mu) * rstd * slnw[d0 + 0] + slnb[d0 + 0]);
            o.y = to_tf32((tv[q * 4 + 1] - mu) * rstd * slnw[d0 + 1] + slnb[d0 + 1]);
            o.z = to_tf32((tv[q * 4 + 2] - mu) * rstd * slnw[d0 + 2] + slnb[d0 + 2]);
            o.w = to_tf32((tv[q * 4 + 3] - mu) * rstd * slnw[d0 + 3] + slnb[d0 + 3]);
            *(float4*)(Bs + r * BS_STRIDE + d0) = o;
        }
        if (kt < 15) { cp_wait<1>(); } else { cp_wait<0>(); }
        __syncthreads();   // Bs + As[buf] ready

        // ---- MMA ----
        const float* as = As[buf];
#pragma unroll
        for (int ks = 0; ks < 2; ks++) {
            int kk = ks * 8;
            uint32_t afr[4][4];
#pragma unroll
            for (int mi = 0; mi < 4; mi++) {
                int rb = wm + mi * 16 + grp;
                int cb = kk + tig;
                afr[mi][0] = __float_as_uint(as[rb * AS_STRIDE + cb]);
                afr[mi][1] = __float_as_uint(as[(rb + 8) * AS_STRIDE + cb]);
                afr[mi][2] = __float_as_uint(as[rb * AS_STRIDE + cb + 4]);
                afr[mi][3] = __float_as_uint(as[(rb + 8) * AS_STRIDE + cb + 4]);
            }
            uint32_t bfr[8][2];
#pragma unroll
            for (int ni = 0; ni < 8; ni++) {
                int nb = wn + ni * 8 + grp;
                int kb = kk + tig;
                bfr[ni][0] = __float_as_uint(Bs[kb * BS_STRIDE + nb]);
                bfr[ni][1] = __float_as_uint(Bs[(kb + 4) * BS_STRIDE + nb]);
            }
#pragma unroll
            for (int mi = 0; mi < 4; mi++)
#pragma unroll
                for (int ni = 0; ni < 8; ni++)
                    mma_tf32(acc[mi][ni],
                             afr[mi][0], afr[mi][1], afr[mi][2], afr[mi][3],
                             bfr[ni][0], bfr[ni][1]);
        }
        // next iteration's first __syncthreads covers the Bs/As hazard
    }

    // epilogue: scale by (1+ew[p]) and add mask[b,p]*eb[b]
    const float* maskb = g_mask + b * 256;
    float ebb = eb[b];
#pragma unroll
    for (int mi = 0; mi < 4; mi++) {
#pragma unroll
        for (int h = 0; h < 2; h++) {
            int p = m0 + wm + mi * 16 + grp + h * 8;
            float scale = 1.0f + ew[p];
            float addv = maskb[p] * ebb;
            long rowoff = ((long)(b * 256 + p)) * 256;
#pragma unroll
            for (int ni = 0; ni < 8; ni++) {
                int d = wn + ni * 8 + tig * 2;
                float v0 = acc[mi][ni][h * 2 + 0] * scale + addv;
                float v1 = acc[mi][ni][h * 2 + 1] * scale + addv;
                *(float2*)(out + rowoff + d) = make_float2(v0, v1);
            }
        }
    }
}

// ---------------- launch -----------------------------------------------------
extern "C" void kernel_launch(void* const* d_in, const int* in_sizes, int n_in,
                              void* d_out, int out_size) {
    const float* x    = (const float*)d_in[0];   // [B,C]
    const float* prev = (const float*)d_in[1];   // [P,D]
    const float* few  = (const float*)d_in[2];   // [C,D]
    const float* feb  = (const float*)d_in[3];   // [1,C,D]
    const float* lnew = (const float*)d_in[4];
    const float* lneb = (const float*)d_in[5];
    const float* lncw = (const float*)d_in[6];
    const float* lncb = (const float*)d_in[7];
    const float* lnpw = (const float*)d_in[8];
    const float* lnpb = (const float*)d_in[9];
    const float* diw  = (const float*)d_in[10];  // [D,2D]
    const float* dib  = (const float*)d_in[11];  // [D]
    const float* embc = (const float*)d_in[12];  // [C,D]
    const float* embp = (const float*)d_in[13];  // [P,D]
    const float* ew   = (const float*)d_in[14];  // [P,1]
    const float* ebia = (const float*)d_in[15];  // [P]
    float* out = (float*)d_out;

    prep_kernel<<<512, 256>>>(embp, lnpw, lnpb, prev, embc, lncw, lncb);
    xprompt_kernel<<<dim3(8, 8), dim3(16, 16)>>>(diw, dib, embp);
    logits_kernel<<<dim3(8, 8), dim3(16, 16)>>>();
    softmax_kernel<<<256, 256>>>();
    out_gemm_fused<<<dim3(2, 256), 256>>>(x, few, feb, lnew, lneb, ew, ebia, out);
}

// round 4
// speedup vs baseline: 1.4180x; 1.4180x over previous
#include <cuda_runtime.h>
#include <cstdint>

// Problem constants: B=C=P=D=256
#define N256 256
#define EPS 1e-5f

// ---------------- scratch (device globals; no allocations allowed) ----------
__device__ float g_xemb[256 * 256 * 256];   // [B,C,D] LN'd embedding, tf32-rounded
__device__ float g_mask[256 * 256];         // [P,C] softmax mask, tf32-rounded
__device__ float g_xprompt[256 * 256];      // [P,D]
__device__ float g_xcol[256 * 256];         // [C,D] LN(emb_column)
__device__ float g_xpin[256 * 512];         // [P,2D] concat(LN(emb_prompt), prev)
__device__ float g_logits[256 * 256];       // [P,C]

// ---------------- helpers ----------------------------------------------------
__device__ __forceinline__ float to_tf32(float x) {
    uint32_t u;
    asm("cvt.rna.tf32.f32 %0, %1;" : "=r"(u) : "f"(x));
    return __uint_as_float(u);
}

__device__ __forceinline__ void cp_async16(void* smem, const void* gmem) {
    uint32_t s = (uint32_t)__cvta_generic_to_shared(smem);
    asm volatile("cp.async.cg.shared.global [%0], [%1], 16;\n" :: "r"(s), "l"(gmem));
}
__device__ __forceinline__ void cp_commit() {
    asm volatile("cp.async.commit_group;\n" ::: "memory");
}
template <int N>
__device__ __forceinline__ void cp_wait() {
    asm volatile("cp.async.wait_group %0;\n" :: "n"(N) : "memory");
}

// dual warp+block reduce for 256-thread blocks (sum of two values), 1 sync
__device__ __forceinline__ void block_sum2_256(float& a, float& b,
                                               float* s8a, float* s8b) {
    int lane = threadIdx.x & 31, wid = threadIdx.x >> 5;
#pragma unroll
    for (int off = 16; off > 0; off >>= 1) {
        a += __shfl_xor_sync(0xffffffff, a, off);
        b += __shfl_xor_sync(0xffffffff, b, off);
    }
    if (lane == 0) { s8a[wid] = a; s8b[wid] = b; }
    __syncthreads();
    a = s8a[0]; b = s8b[0];
#pragma unroll
    for (int i = 1; i < 8; i++) { a += s8a[i]; b += s8b[i]; }
}

// ---------------- K1: prep — xpin rows (blocks 0..255), xcol rows (256..511) -
__global__ void prep_kernel(const float* __restrict__ embp,
                            const float* __restrict__ lnpw,
                            const float* __restrict__ lnpb,
                            const float* __restrict__ prev,
                            const float* __restrict__ embc,
                            const float* __restrict__ lncw,
                            const float* __restrict__ lncb) {
    __shared__ float s8a[8], s8b[8];
    int d = threadIdx.x;
    if (blockIdx.x < 256) {
        int p = blockIdx.x;
        float v = embp[p * N256 + d];
        float a = v, bq = v * v;
        block_sum2_256(a, bq, s8a, s8b);
        float mu = a * (1.0f / 256.0f);
        float var = bq * (1.0f / 256.0f) - mu * mu;
        float rstd = rsqrtf(var + EPS);
        g_xpin[p * 512 + d] = (v - mu) * rstd * lnpw[d] + lnpb[d];
        g_xpin[p * 512 + 256 + d] = prev[p * N256 + d];
    } else {
        int c = blockIdx.x - 256;
        float v = embc[c * N256 + d];
        float a = v, bq = v * v;
        block_sum2_256(a, bq, s8a, s8b);
        float mu = a * (1.0f / 256.0f);
        float var = bq * (1.0f / 256.0f) - mu * mu;
        float rstd = rsqrtf(var + EPS);
        g_xcol[c * N256 + d] = (v - mu) * rstd * lncw[d] + lncb[d];
    }
}

// ---------------- K2: x_prompt = xp_in @ W^T + b + emb_prompt ---------------
// M=256(p) x N=256(d) x K=512, 32x32 tiles, 2x2 per thread.
__global__ void xprompt_kernel(const float* __restrict__ W,
                               const float* __restrict__ bias,
                               const float* __restrict__ embp) {
    __shared__ float As[32][17];
    __shared__ float Ws[32][17];
    int tx = threadIdx.x, ty = threadIdx.y;
    int t = ty * 16 + tx;
    int p0 = blockIdx.y * 32;
    int d0 = blockIdx.x * 32;
    float acc[2][2] = {{0.f, 0.f}, {0.f, 0.f}};
    for (int kt = 0; kt < 32; kt++) {
        int k0 = kt * 16;
#pragma unroll
        for (int i = 0; i < 2; i++) {
            int idx = i * 256 + t;
            int r = idx >> 4, k = idx & 15;
            As[r][k] = g_xpin[(p0 + r) * 512 + k0 + k];
            Ws[r][k] = W[(d0 + r) * 512 + k0 + k];
        }
        __syncthreads();
#pragma unroll
        for (int kk = 0; kk < 16; kk++) {
            float a0 = As[ty * 2][kk], a1 = As[ty * 2 + 1][kk];
            float b0 = Ws[tx * 2][kk], b1 = Ws[tx * 2 + 1][kk];
            acc[0][0] += a0 * b0; acc[0][1] += a0 * b1;
            acc[1][0] += a1 * b0; acc[1][1] += a1 * b1;
        }
        __syncthreads();
    }
#pragma unroll
    for (int i = 0; i < 2; i++)
#pragma unroll
        for (int j = 0; j < 2; j++) {
            int p = p0 + ty * 2 + i, dd = d0 + tx * 2 + j;
            g_xprompt[p * N256 + dd] = acc[i][j] + bias[dd] + embp[p * N256 + dd];
        }
}

// ---------------- K3: logits = x_prompt @ x_col^T (32x32 tiles, 2x2/thread) -
__global__ void logits_kernel() {
    __shared__ float As[32][17];
    __shared__ float Bs[32][17];
    int tx = threadIdx.x, ty = threadIdx.y;
    int t = ty * 16 + tx;
    int p0 = blockIdx.y * 32;
    int c0 = blockIdx.x * 32;
    float acc[2][2] = {{0.f, 0.f}, {0.f, 0.f}};
    for (int kt = 0; kt < 16; kt++) {
        int k0 = kt * 16;
#pragma unroll
        for (int i = 0; i < 2; i++) {
            int idx = i * 256 + t;
            int r = idx >> 4, k = idx & 15;
            As[r][k] = g_xprompt[(p0 + r) * N256 + k0 + k];
            Bs[r][k] = g_xcol[(c0 + r) * N256 + k0 + k];
        }
        __syncthreads();
#pragma unroll
        for (int kk = 0; kk < 16; kk++) {
            float a0 = As[ty * 2][kk], a1 = As[ty * 2 + 1][kk];
            float b0 = Bs[tx * 2][kk], b1 = Bs[tx * 2 + 1][kk];
            acc[0][0] += a0 * b0; acc[0][1] += a0 * b1;
            acc[1][0] += a1 * b0; acc[1][1] += a1 * b1;
        }
        __syncthreads();
    }
#pragma unroll
    for (int i = 0; i < 2; i++)
#pragma unroll
        for (int j = 0; j < 2; j++)
            g_logits[(p0 + ty * 2 + i) * N256 + c0 + tx * 2 + j] = acc[i][j];
}

// ---------------- K4: row softmax (warp-shuffle), tf32-rounded --------------
__global__ void softmax_kernel() {
    __shared__ float sw[8];
    int p = blockIdx.x, c = threadIdx.x;
    int lane = c & 31, wid = c >> 5;
    float v = g_logits[p * N256 + c];
    float m = v;
#pragma unroll
    for (int off = 16; off > 0; off >>= 1)
        m = fmaxf(m, __shfl_xor_sync(0xffffffff, m, off));
    if (lane == 0) sw[wid] = m;
    __syncthreads();
    float mx = sw[0];
#pragma unroll
    for (int i = 1; i < 8; i++) mx = fmaxf(mx, sw[i]);
    float e = expf(v - mx);
    float s = e;
#pragma unroll
    for (int off = 16; off > 0; off >>= 1)
        s += __shfl_xor_sync(0xffffffff, s, off);
    __syncthreads();             // everyone done reading sw (max phase)
    if (lane == 0) sw[wid] = s;
    __syncthreads();
    float sum = sw[0];
#pragma unroll
    for (int i = 1; i < 8; i++) sum += sw[i];
    g_mask[p * N256 + c] = to_tf32(e / sum);
}

// ---------------- K5: x_emb = LN(relu(bias + x*w)), tf32-rounded ------------
// one warp per (b,c) row; 8 warps per block
__global__ void xemb_kernel(const float* __restrict__ x,
                            const float* __restrict__ few,
                            const float* __restrict__ feb,
                            const float* __restrict__ lnew,
                            const float* __restrict__ lneb) {
    int lane = threadIdx.x & 31;
    int wid = threadIdx.x >> 5;
    int row = blockIdx.x * 8 + wid;            // = b*256 + c
    int c = row & 255;
    const float xv = x[row];
    const float* wrow = few + c * N256;
    const float* brow = feb + c * N256;
    float v[8];
    float sum = 0.0f, sq = 0.0f;
#pragma unroll
    for (int i = 0; i < 8; i++) {
        int d = lane + i * 32;
        float t = fmaf(xv, wrow[d], brow[d]);
        t = t > 0.0f ? t : 0.0f;
        v[i] = t;
        sum += t;
        sq = fmaf(t, t, sq);
    }
#pragma unroll
    for (int off = 16; off > 0; off >>= 1) {
        sum += __shfl_xor_sync(0xffffffff, sum, off);
        sq  += __shfl_xor_sync(0xffffffff, sq, off);
    }
    float mu = sum * (1.0f / 256.0f);
    float var = sq * (1.0f / 256.0f) - mu * mu;
    float rstd = rsqrtf(var + EPS);
    float* orow = g_xemb + row * N256;
#pragma unroll
    for (int i = 0; i < 8; i++) {
        int d = lane + i * 32;
        orow[d] = to_tf32((v[i] - mu) * rstd * lnew[d] + lneb[d]);
    }
}

// ---------------- K6: out[b] = mask @ xemb[b], tf32 mma ---------------------
// out[0,b,p,d] = (1+ew[p]) * sum_c mask[p,c]*xemb[b,c,d] + mask[b,p]*eb[b]
// Block tile 128(m) x 256(n), K-chunk 16, double-buffered cp.async on A and B.
// Grid (2 m-tiles, 256 b). 8 warps: 2 along m (64) x 4 along n (64).
__device__ __forceinline__ void mma_tf32(float c[4],
                                         uint32_t a0, uint32_t a1, uint32_t a2, uint32_t a3,
                                         uint32_t b0, uint32_t b1) {
    asm volatile(
        "mma.sync.aligned.m16n8k8.row.col.f32.tf32.tf32.f32 "
        "{%0,%1,%2,%3}, {%4,%5,%6,%7}, {%8,%9}, {%0,%1,%2,%3};"
        : "+f"(c[0]), "+f"(c[1]), "+f"(c[2]), "+f"(c[3])
        : "r"(a0), "r"(a1), "r"(a2), "r"(a3), "r"(b0), "r"(b1));
}

#define AS_STRIDE 20    // 16 + 4 pad   (A-frag LDS conflict-free)
#define BS_STRIDE 264   // 256 + 8 pad  (264 mod 32 = 8 -> B-frag conflict-free)
#define AS_BUF (128 * AS_STRIDE)
#define BS_BUF (16 * BS_STRIDE)
#define GEMM_SMEM_BYTES ((2 * AS_BUF + 2 * BS_BUF) * 4)

__global__ __launch_bounds__(256, 1) void out_gemm_kernel(
    const float* __restrict__ ew,
    const float* __restrict__ eb,
    float* __restrict__ out) {
    extern __shared__ __align__(16) float smem[];
    float* As = smem;                 // [2][128*AS_STRIDE]
    float* Bs = smem + 2 * AS_BUF;    // [2][16*BS_STRIDE]

    int m0 = blockIdx.x * 128;
    int b = blockIdx.y;
    const float* A = g_mask;                 // [P=256, C=256]
    const float* B = g_xemb + b * 65536;     // [C=256, D=256]

    int tid = threadIdx.x;
    int lane = tid & 31;
    int warp = tid >> 5;
    int wm = (warp & 1) * 64;
    int wn = (warp >> 1) * 64;
    int grp = lane >> 2;      // 0..7
    int tig = lane & 3;       // 0..3

    float acc[4][8][4];
#pragma unroll
    for (int i = 0; i < 4; i++)
#pragma unroll
        for (int j = 0; j < 8; j++)
#pragma unroll
            for (int k = 0; k < 4; k++) acc[i][j][k] = 0.0f;

    auto load_tiles = [&](int buf, int kt) {
        int k0 = kt * 16;
        // A tile: 128 rows x 16 k = 512 float4 (2/thread)
#pragma unroll
        for (int t = 0; t < 2; t++) {
            int idx = t * 256 + tid;
            int r = idx >> 2;
            int kc = (idx & 3) << 2;
            cp_async16(As + buf * AS_BUF + r * AS_STRIDE + kc,
                       A + (m0 + r) * 256 + k0 + kc);
        }
        // B tile: 16 k x 256 n = 1024 float4 (4/thread)
#pragma unroll
        for (int t = 0; t < 4; t++) {
            int idx = t * 256 + tid;
            int r = idx >> 6;
            int nc = (idx & 63) << 2;
            cp_async16(Bs + buf * BS_BUF + r * BS_STRIDE + nc,
                       B + (k0 + r) * 256 + nc);
        }
        cp_commit();
    };

    load_tiles(0, 0);

    for (int kt = 0; kt < 16; kt++) {
        int buf = kt & 1;
        if (kt < 15) {
            load_tiles(buf ^ 1, kt + 1);
            cp_wait<1>();
        } else {
            cp_wait<0>();
        }
        __syncthreads();

        const float* as = As + buf * AS_BUF;
        const float* bs = Bs + buf * BS_BUF;
#pragma unroll
        for (int ks = 0; ks < 2; ks++) {
            int kk = ks * 8;
            uint32_t afr[4][4];
#pragma unroll
            for (int mi = 0; mi < 4; mi++) {
                int rb = wm + mi * 16 + grp;
                int cb = kk + tig;
                afr[mi][0] = __float_as_uint(as[rb * AS_STRIDE + cb]);
                afr[mi][1] = __float_as_uint(as[(rb + 8) * AS_STRIDE + cb]);
                afr[mi][2] = __float_as_uint(as[rb * AS_STRIDE + cb + 4]);
                afr[mi][3] = __float_as_uint(as[(rb + 8) * AS_STRIDE + cb + 4]);
            }
            uint32_t bfr[8][2];
#pragma unroll
            for (int ni = 0; ni < 8; ni++) {
                int nb = wn + ni * 8 + grp;
                int kb = kk + tig;
                bfr[ni][0] = __float_as_uint(bs[kb * BS_STRIDE + nb]);
                bfr[ni][1] = __float_as_uint(bs[(kb + 4) * BS_STRIDE + nb]);
            }
#pragma unroll
            for (int mi = 0; mi < 4; mi++)
#pragma unroll
                for (int ni = 0; ni < 8; ni++)
                    mma_tf32(acc[mi][ni],
                             afr[mi][0], afr[mi][1], afr[mi][2], afr[mi][3],
                             bfr[ni][0], bfr[ni][1]);
        }
        __syncthreads();
    }

    // epilogue: scale by (1+ew[p]) and add mask[b,p]*eb[b]
    const float* maskb = g_mask + b * 256;
    float ebb = eb[b];
#pragma unroll
    for (int mi = 0; mi < 4; mi++) {
#pragma unroll
        for (int h = 0; h < 2; h++) {
            int p = m0 + wm + mi * 16 + grp + h * 8;
            float scale = 1.0f + ew[p];
            float addv = maskb[p] * ebb;
            long rowoff = ((long)(b * 256 + p)) * 256;
#pragma unroll
            for (int ni = 0; ni < 8; ni++) {
                int d = wn + ni * 8 + tig * 2;
                float v0 = acc[mi][ni][h * 2 + 0] * scale + addv;
                float v1 = acc[mi][ni][h * 2 + 1] * scale + addv;
                *(float2*)(out + rowoff + d) = make_float2(v0, v1);
            }
        }
    }
}

// ---------------- launch -----------------------------------------------------
extern "C" void kernel_launch(void* const* d_in, const int* in_sizes, int n_in,
                              void* d_out, int out_size) {
    const float* x    = (const float*)d_in[0];   // [B,C]
    const float* prev = (const float*)d_in[1];   // [P,D]
    const float* few  = (const float*)d_in[2];   // [C,D]
    const float* feb  = (const float*)d_in[3];   // [1,C,D]
    const float* lnew = (const float*)d_in[4];
    const float* lneb = (const float*)d_in[5];
    const float* lncw = (const float*)d_in[6];
    const float* lncb = (const float*)d_in[7];
    const float* lnpw = (const float*)d_in[8];
    const float* lnpb = (const float*)d_in[9];
    const float* diw  = (const float*)d_in[10];  // [D,2D]
    const float* dib  = (const float*)d_in[11];  // [D]
    const float* embc = (const float*)d_in[12];  // [C,D]
    const float* embp = (const float*)d_in[13];  // [P,D]
    const float* ew   = (const float*)d_in[14];  // [P,1]
    const float* ebia = (const float*)d_in[15];  // [P]
    float* out = (float*)d_out;

    static bool attr_set = false;
    if (!attr_set) {
        cudaFuncSetAttribute(out_gemm_kernel,
                             cudaFuncAttributeMaxDynamicSharedMemorySize,
                             GEMM_SMEM_BYTES);
        attr_set = true;
    }

    prep_kernel<<<512, 256>>>(embp, lnpw, lnpb, prev, embc, lncw, lncb);
    xprompt_kernel<<<dim3(8, 8), dim3(16, 16)>>>(diw, dib, embp);
    logits_kernel<<<dim3(8, 8), dim3(16, 16)>>>();
    softmax_kernel<<<256, 256>>>();
    xemb_kernel<<<8192, 256>>>(x, few, feb, lnew, lneb);
    out_gemm_kernel<<<dim3(2, 256), 256, GEMM_SMEM_BYTES>>>(ew, ebia, out);
}

// round 5
// speedup vs baseline: 1.5281x; 1.0777x over previous
#include <cuda_runtime.h>
#include <cstdint>

// Problem constants: B=C=P=D=256
#define N256 256
#define EPS 1e-5f

// ---------------- scratch (device globals; no allocations allowed) ----------
__device__ float g_xemb[256 * 256 * 256];   // [B,C,D] LN'd embedding, tf32-rounded
__device__ float g_mask[256 * 256];         // [P,C] softmax mask, tf32-rounded
__device__ float g_xprompt[256 * 256];      // [P,D]
__device__ float g_xcol[256 * 256];         // [C,D] LN(emb_column)
__device__ float g_xpin[256 * 512];         // [P,2D] concat(LN(emb_prompt), prev)
__device__ float g_logits[256 * 256];       // [P,C]

// ---------------- helpers ----------------------------------------------------
__device__ __forceinline__ float to_tf32(float x) {
    uint32_t u;
    asm("cvt.rna.tf32.f32 %0, %1;" : "=r"(u) : "f"(x));
    return __uint_as_float(u);
}

__device__ __forceinline__ void cp_async16(void* smem, const void* gmem) {
    uint32_t s = (uint32_t)__cvta_generic_to_shared(smem);
    asm volatile("cp.async.cg.shared.global [%0], [%1], 16;\n" :: "r"(s), "l"(gmem));
}
__device__ __forceinline__ void cp_commit() {
    asm volatile("cp.async.commit_group;\n" ::: "memory");
}
template <int N>
__device__ __forceinline__ void cp_wait() {
    asm volatile("cp.async.wait_group %0;\n" :: "n"(N) : "memory");
}

// dual warp+block reduce for 256-thread blocks (sum of two values)
__device__ __forceinline__ void block_sum2_256(float& a, float& b,
                                               float* s8a, float* s8b) {
    int lane = threadIdx.x & 31, wid = threadIdx.x >> 5;
#pragma unroll
    for (int off = 16; off > 0; off >>= 1) {
        a += __shfl_xor_sync(0xffffffff, a, off);
        b += __shfl_xor_sync(0xffffffff, b, off);
    }
    if (lane == 0) { s8a[wid] = a; s8b[wid] = b; }
    __syncthreads();
    a = s8a[0]; b = s8b[0];
#pragma unroll
    for (int i = 1; i < 8; i++) { a += s8a[i]; b += s8b[i]; }
}

// ---------------- K1: xemb (blocks 0..8191) + prep (blocks 8192..8703) ------
// xemb: block = (c, 8-b group). few[c]/feb[c] cached in smem, 8 warps x 8 b's.
// prep: LN(emb_prompt)->xpin / LN(emb_column)->xcol.
__global__ void xemb_prep_kernel(const float* __restrict__ x,
                                 const float* __restrict__ few,
                                 const float* __restrict__ feb,
                                 const float* __restrict__ lnew,
                                 const float* __restrict__ lneb,
                                 const float* __restrict__ embp,
                                 const float* __restrict__ lnpw,
                                 const float* __restrict__ lnpb,
                                 const float* __restrict__ prev,
                                 const float* __restrict__ embc,
                                 const float* __restrict__ lncw,
                                 const float* __restrict__ lncb) {
    __shared__ float sbuf[4 * 256 + 16];
    int tid = threadIdx.x;
    if (blockIdx.x < 8192) {
        float* sw  = sbuf;             // few[c,:]
        float* sb  = sbuf + 256;       // feb[c,:]
        float* slw = sbuf + 512;       // lnew
        float* slb = sbuf + 768;       // lneb
        int c  = blockIdx.x >> 5;
        int bg = blockIdx.x & 31;
        sw[tid]  = few[c * 256 + tid];
        sb[tid]  = feb[c * 256 + tid];
        slw[tid] = lnew[tid];
        slb[tid] = lneb[tid];
        __syncthreads();

        int lane = tid & 31;
        int wid = tid >> 5;
        int b = bg * 8 + wid;
        float xv = x[b * 256 + c];
        float v[8];
        float sum = 0.0f, sq = 0.0f;
#pragma unroll
        for (int i = 0; i < 8; i++) {
            int d = lane + i * 32;
            float t = fmaf(xv, sw[d], sb[d]);
            t = t > 0.0f ? t : 0.0f;
            v[i] = t;
            sum += t;
            sq = fmaf(t, t, sq);
        }
#pragma unroll
        for (int off = 16; off > 0; off >>= 1) {
            sum += __shfl_xor_sync(0xffffffff, sum, off);
            sq  += __shfl_xor_sync(0xffffffff, sq, off);
        }
        float mu = sum * (1.0f / 256.0f);
        float var = sq * (1.0f / 256.0f) - mu * mu;
        float rstd = rsqrtf(var + EPS);
        float* orow = g_xemb + ((long)b * 256 + c) * 256;
#pragma unroll
        for (int i = 0; i < 8; i++) {
            int d = lane + i * 32;
            orow[d] = to_tf32((v[i] - mu) * rstd * slw[d] + slb[d]);
        }
    } else {
        float* s8a = sbuf;
        float* s8b = sbuf + 8;
        int blk = blockIdx.x - 8192;   // 0..511
        int d = tid;
        if (blk < 256) {
            int p = blk;
            float v = embp[p * N256 + d];
            float a = v, bq = v * v;
            block_sum2_256(a, bq, s8a, s8b);
            float mu = a * (1.0f / 256.0f);
            float var = bq * (1.0f / 256.0f) - mu * mu;
            float rstd = rsqrtf(var + EPS);
            g_xpin[p * 512 + d] = (v - mu) * rstd * lnpw[d] + lnpb[d];
            g_xpin[p * 512 + 256 + d] = prev[p * N256 + d];
        } else {
            int c = blk - 256;
            float v = embc[c * N256 + d];
            float a = v, bq = v * v;
            block_sum2_256(a, bq, s8a, s8b);
            float mu = a * (1.0f / 256.0f);
            float var = bq * (1.0f / 256.0f) - mu * mu;
            float rstd = rsqrtf(var + EPS);
            g_xcol[c * N256 + d] = (v - mu) * rstd * lncw[d] + lncb[d];
        }
    }
}

// ---------------- K2: x_prompt = xp_in @ W^T + b + emb_prompt ---------------
// M=256(p) x N=256(d) x K=512, 32x32 tiles, 2x2 per thread.
__global__ void xprompt_kernel(const float* __restrict__ W,
                               const float* __restrict__ bias,
                               const float* __restrict__ embp) {
    __shared__ float As[32][17];
    __shared__ float Ws[32][17];
    int tx = threadIdx.x, ty = threadIdx.y;
    int t = ty * 16 + tx;
    int p0 = blockIdx.y * 32;
    int d0 = blockIdx.x * 32;
    float acc[2][2] = {{0.f, 0.f}, {0.f, 0.f}};
    for (int kt = 0; kt < 32; kt++) {
        int k0 = kt * 16;
#pragma unroll
        for (int i = 0; i < 2; i++) {
            int idx = i * 256 + t;
            int r = idx >> 4, k = idx & 15;
            As[r][k] = g_xpin[(p0 + r) * 512 + k0 + k];
            Ws[r][k] = W[(d0 + r) * 512 + k0 + k];
        }
        __syncthreads();
#pragma unroll
        for (int kk = 0; kk < 16; kk++) {
            float a0 = As[ty * 2][kk], a1 = As[ty * 2 + 1][kk];
            float b0 = Ws[tx * 2][kk], b1 = Ws[tx * 2 + 1][kk];
            acc[0][0] += a0 * b0; acc[0][1] += a0 * b1;
            acc[1][0] += a1 * b0; acc[1][1] += a1 * b1;
        }
        __syncthreads();
    }
#pragma unroll
    for (int i = 0; i < 2; i++)
#pragma unroll
        for (int j = 0; j < 2; j++) {
            int p = p0 + ty * 2 + i, dd = d0 + tx * 2 + j;
            g_xprompt[p * N256 + dd] = acc[i][j] + bias[dd] + embp[p * N256 + dd];
        }
}

// ---------------- K3: logits = x_prompt @ x_col^T (32x32 tiles, 2x2/thread) -
__global__ void logits_kernel() {
    __shared__ float As[32][17];
    __shared__ float Bs[32][17];
    int tx = threadIdx.x, ty = threadIdx.y;
    int t = ty * 16 + tx;
    int p0 = blockIdx.y * 32;
    int c0 = blockIdx.x * 32;
    float acc[2][2] = {{0.f, 0.f}, {0.f, 0.f}};
    for (int kt = 0; kt < 16; kt++) {
        int k0 = kt * 16;
#pragma unroll
        for (int i = 0; i < 2; i++) {
            int idx = i * 256 + t;
            int r = idx >> 4, k = idx & 15;
            As[r][k] = g_xprompt[(p0 + r) * N256 + k0 + k];
            Bs[r][k] = g_xcol[(c0 + r) * N256 + k0 + k];
        }
        __syncthreads();
#pragma unroll
        for (int kk = 0; kk < 16; kk++) {
            float a0 = As[ty * 2][kk], a1 = As[ty * 2 + 1][kk];
            float b0 = Bs[tx * 2][kk], b1 = Bs[tx * 2 + 1][kk];
            acc[0][0] += a0 * b0; acc[0][1] += a0 * b1;
            acc[1][0] += a1 * b0; acc[1][1] += a1 * b1;
        }
        __syncthreads();
    }
#pragma unroll
    for (int i = 0; i < 2; i++)
#pragma unroll
        for (int j = 0; j < 2; j++)
            g_logits[(p0 + ty * 2 + i) * N256 + c0 + tx * 2 + j] = acc[i][j];
}

// ---------------- K4: row softmax (warp-shuffle), tf32-rounded --------------
__global__ void softmax_kernel() {
    __shared__ float sw[8];
    int p = blockIdx.x, c = threadIdx.x;
    int lane = c & 31, wid = c >> 5;
    float v = g_logits[p * N256 + c];
    float m = v;
#pragma unroll
    for (int off = 16; off > 0; off >>= 1)
        m = fmaxf(m, __shfl_xor_sync(0xffffffff, m, off));
    if (lane == 0) sw[wid] = m;
    __syncthreads();
    float mx = sw[0];
#pragma unroll
    for (int i = 1; i < 8; i++) mx = fmaxf(mx, sw[i]);
    float e = expf(v - mx);
    float s = e;
#pragma unroll
    for (int off = 16; off > 0; off >>= 1)
        s += __shfl_xor_sync(0xffffffff, s, off);
    __syncthreads();
    if (lane == 0) sw[wid] = s;
    __syncthreads();
    float sum = sw[0];
#pragma unroll
    for (int i = 1; i < 8; i++) sum += sw[i];
    g_mask[p * N256 + c] = to_tf32(e / sum);
}

// ---------------- K5: out[b] = mask @ xemb[b], tf32 mma ---------------------
// out[0,b,p,d] = (1+ew[p]) * sum_c mask[p,c]*xemb[b,c,d] + mask[b,p]*eb[b]
// Block tile 128x128, K-chunk 16, double-buffered cp.async, 2 blocks/SM forced.
__device__ __forceinline__ void mma_tf32(float c[4],
                                         uint32_t a0, uint32_t a1, uint32_t a2, uint32_t a3,
                                         uint32_t b0, uint32_t b1) {
    asm volatile(
        "mma.sync.aligned.m16n8k8.row.col.f32.tf32.tf32.f32 "
        "{%0,%1,%2,%3}, {%4,%5,%6,%7}, {%8,%9}, {%0,%1,%2,%3};"
        : "+f"(c[0]), "+f"(c[1]), "+f"(c[2]), "+f"(c[3])
        : "r"(a0), "r"(a1), "r"(a2), "r"(a3), "r"(b0), "r"(b1));
}

#define AS_STRIDE 20    // 16 + 4 pad
#define BS_STRIDE 136   // 128 + 8 pad (136 mod 32 = 8 -> B-frag reads conflict-free)

__global__ __launch_bounds__(256, 2) void out_gemm_kernel(
    const float* __restrict__ ew,
    const float* __restrict__ eb,
    float* __restrict__ out) {
    __shared__ __align__(16) float As[2][128 * AS_STRIDE];
    __shared__ __align__(16) float Bs[2][16 * BS_STRIDE];

    int b = blockIdx.z;
    int m0 = blockIdx.y * 128;
    int n0 = blockIdx.x * 128;
    const float* A = g_mask;                 // [P=256, C=256]
    const float* B = g_xemb + b * 65536;     // [C=256, D=256]

    int tid = threadIdx.x;
    int lane = tid & 31;
    int warp = tid >> 5;
    int wm = (warp & 1) * 64;
    int wn = (warp >> 1) * 32;
    int grp = lane >> 2;      // 0..7
    int tig = lane & 3;       // 0..3

    float acc[4][4][4];
#pragma unroll
    for (int i = 0; i < 4; i++)
#pragma unroll
        for (int j = 0; j < 4; j++)
#pragma unroll
            for (int k = 0; k < 4; k++) acc[i][j][k] = 0.0f;

    auto load_tiles = [&](int buf, int kt) {
        int k0 = kt * 16;
#pragma unroll
        for (int t = 0; t < 2; t++) {
            int idx = t * 256 + tid;
            int r = idx >> 2;
            int kc = (idx & 3) << 2;
            cp_async16(&As[buf][r * AS_STRIDE + kc],
                       A + (m0 + r) * 256 + k0 + kc);
            int rb = idx >> 5;
            int nc = (idx & 31) << 2;
            cp_async16(&Bs[buf][rb * BS_STRIDE + nc],
                       B + (k0 + rb) * 256 + n0 + nc);
        }
        cp_commit();
    };

    load_tiles(0, 0);

    for (int kt = 0; kt < 16; kt++) {
        int buf = kt & 1;
        if (kt < 15) {
            load_tiles(buf ^ 1, kt + 1);
            cp_wait<1>();
        } else {
            cp_wait<0>();
        }
        __syncthreads();

        const float* as = As[buf];
        const float* bs = Bs[buf];
#pragma unroll
        for (int ks = 0; ks < 2; ks++) {
            int kk = ks * 8;
            uint32_t afr[4][4];
#pragma unroll
            for (int mi = 0; mi < 4; mi++) {
                int rb = wm + mi * 16 + grp;
                int cb = kk + tig;
                afr[mi][0] = __float_as_uint(as[rb * AS_STRIDE + cb]);
                afr[mi][1] = __float_as_uint(as[(rb + 8) * AS_STRIDE + cb]);
                afr[mi][2] = __float_as_uint(as[rb * AS_STRIDE + cb + 4]);
                afr[mi][3] = __float_as_uint(as[(rb + 8) * AS_STRIDE + cb + 4]);
            }
            uint32_t bfr[4][2];
#pragma unroll
            for (int ni = 0; ni < 4; ni++) {
                int nb = wn + ni * 8 + grp;
                int kb = kk + tig;
                bfr[ni][0] = __float_as_uint(bs[kb * BS_STRIDE + nb]);
                bfr[ni][1] = __float_as_uint(bs[(kb + 4) * BS_STRIDE + nb]);
            }
#pragma unroll
            for (int mi = 0; mi < 4; mi++)
#pragma unroll
                for (int ni = 0; ni < 4; ni++)
                    mma_tf32(acc[mi][ni],
                             afr[mi][0], afr[mi][1], afr[mi][2], afr[mi][3],
                             bfr[ni][0], bfr[ni][1]);
        }
        __syncthreads();
    }

    // epilogue
    const float* maskb = g_mask + b * 256;
    float ebb = eb[b];
#pragma unroll
    for (int mi = 0; mi < 4; mi++) {
#pragma unroll
        for (int h = 0; h < 2; h++) {
            int p = m0 + wm + mi * 16 + grp + h * 8;
            float scale = 1.0f + ew[p];
            float addv = maskb[p] * ebb;
            long rowoff = ((long)(b * 256 + p)) * 256;
#pragma unroll
            for (int ni = 0; ni < 4; ni++) {
                int d = n0 + wn + ni * 8 + tig * 2;
                float v0 = acc[mi][ni][h * 2 + 0] * scale + addv;
                float v1 = acc[mi][ni][h * 2 + 1] * scale + addv;
                *(float2*)(out + rowoff + d) = make_float2(v0, v1);
            }
        }
    }
}

// ---------------- launch -----------------------------------------------------
extern "C" void kernel_launch(void* const* d_in, const int* in_sizes, int n_in,
                              void* d_out, int out_size) {
    const float* x    = (const float*)d_in[0];   // [B,C]
    const float* prev = (const float*)d_in[1];   // [P,D]
    const float* few  = (const float*)d_in[2];   // [C,D]
    const float* feb  = (const float*)d_in[3];   // [1,C,D]
    const float* lnew = (const float*)d_in[4];
    const float* lneb = (const float*)d_in[5];
    const float* lncw = (const float*)d_in[6];
    const float* lncb = (const float*)d_in[7];
    const float* lnpw = (const float*)d_in[8];
    const float* lnpb = (const float*)d_in[9];
    const float* diw  = (const float*)d_in[10];  // [D,2D]
    const float* dib  = (const float*)d_in[11];  // [D]
    const float* embc = (const float*)d_in[12];  // [C,D]
    const float* embp = (const float*)d_in[13];  // [P,D]
    const float* ew   = (const float*)d_in[14];  // [P,1]
    const float* ebia = (const float*)d_in[15];  // [P]
    float* out = (float*)d_out;

    xemb_prep_kernel<<<8704, 256>>>(x, few, feb, lnew, lneb,
                                    embp, lnpw, lnpb, prev, embc, lncw, lncb);
    xprompt_kernel<<<dim3(8, 8), dim3(16, 16)>>>(diw, dib, embp);
    logits_kernel<<<dim3(8, 8), dim3(16, 16)>>>();
    softmax_kernel<<<256, 256>>>();
    out_gemm_kernel<<<dim3(2, 2, 256), 256>>>(ew, ebia, out);
}

// round 7
// speedup vs baseline: 1.9902x; 1.3024x over previous
#include <cuda_runtime.h>
#include <cuda_fp16.h>
#include <cstdint>

// Problem constants: B=C=P=D=256
#define N256 256
#define EPS 1e-5f

// ---------------- scratch (device globals; no allocations allowed) ----------
__device__ __half2 g_xembh[256 * 128 * 256]; // [b][c/2][d] k-pair-packed halves
__device__ __half2 g_maskh[256 * 128];       // [p][c/2] k-pair-packed halves
__device__ float g_mask_row[256 * 256];      // [p][c] fp32 copy (for epilogue bias)
__device__ float g_xprompt[256 * 256];       // [P,D]
__device__ float g_xcol[256 * 256];          // [C,D] LN(emb_column)
__device__ float g_xpin[256 * 512];          // [P,2D]
__device__ float g_logits[256 * 256];        // [P,C]

// ---------------- helpers ----------------------------------------------------
__device__ __forceinline__ void cp_async16(void* smem, const void* gmem) {
    uint32_t s = (uint32_t)__cvta_generic_to_shared(smem);
    asm volatile("cp.async.cg.shared.global [%0], [%1], 16;" :: "r"(s), "l"(gmem));
}
__device__ __forceinline__ void cp_commit() {
    asm volatile("cp.async.commit_group;" ::: "memory");
}
template <int N>
__device__ __forceinline__ void cp_wait() {
    asm volatile("cp.async.wait_group %0;" :: "n"(N) : "memory");
}

// dual warp+block reduce
__device__ __forceinline__ void block_sum2_256(float& a, float& b,
                                               float* s8a, float* s8b) {
    int lane = threadIdx.x & 31, wid = threadIdx.x >> 5;
#pragma unroll
    for (int off = 16; off > 0; off >>= 1) {
        a += __shfl_xor_sync(0xffffffff, a, off);
        b += __shfl_xor_sync(0xffffffff, b, off);
    }
    if (lane == 0) { s8a[wid] = a; s8b[wid] = b; }
    __syncthreads();
    a = s8a[0]; b = s8b[0];
#pragma unroll
    for (int i = 1; i < 8; i++) { a += s8a[i]; b += s8b[i]; }
}

// ---------------- K1: xemb pairs (blocks 0..4095) + prep (4096..4607) -------
// xemb: block = (c-pair, 8-b group). Each warp computes LN rows (b,c0) and
// (b,c1), packs {v0,v1} as half2 -> g_xembh[b][c2][d] (coalesced).
__global__ void xemb_prep_kernel(const float* __restrict__ x,
                                 const float* __restrict__ few,
                                 const float* __restrict__ feb,
                                 const float* __restrict__ lnew,
                                 const float* __restrict__ lneb,
                                 const float* __restrict__ embp,
                                 const float* __restrict__ lnpw,
                                 const float* __restrict__ lnpb,
                                 const float* __restrict__ prev,
                                 const float* __restrict__ embc,
                                 const float* __restrict__ lncw,
                                 const float* __restrict__ lncb) {
    __shared__ float sbuf[6 * 256 + 16];
    int tid = threadIdx.x;
    if (blockIdx.x < 4096) {
        float* sw0 = sbuf;             // few[c0,:]
        float* sb0 = sbuf + 256;       // feb[c0,:]
        float* sw1 = sbuf + 512;       // few[c1,:]
        float* sb1 = sbuf + 768;       // feb[c1,:]
        float* slw = sbuf + 1024;      // lnew
        float* slb = sbuf + 1280;      // lneb
        int c2 = blockIdx.x >> 5;      // 0..127
        int bg = blockIdx.x & 31;
        int c0 = c2 * 2, c1 = c0 + 1;
        sw0[tid] = few[c0 * 256 + tid];
        sb0[tid] = feb[c0 * 256 + tid];
        sw1[tid] = few[c1 * 256 + tid];
        sb1[tid] = feb[c1 * 256 + tid];
        slw[tid] = lnew[tid];
        slb[tid] = lneb[tid];
        __syncthreads();

        int lane = tid & 31;
        int wid = tid >> 5;
        int b = bg * 8 + wid;
        float xv0 = x[b * 256 + c0];
        float xv1 = x[b * 256 + c1];
        float v0[8], v1[8];
        float s0 = 0.f, q0 = 0.f, s1 = 0.f, q1 = 0.f;
#pragma unroll
        for (int i = 0; i < 8; i++) {
            int d = lane + i * 32;
            float t0 = fmaf(xv0, sw0[d], sb0[d]);
            float t1 = fmaf(xv1, sw1[d], sb1[d]);
            t0 = t0 > 0.f ? t0 : 0.f;
            t1 = t1 > 0.f ? t1 : 0.f;
            v0[i] = t0; v1[i] = t1;
            s0 += t0; q0 = fmaf(t0, t0, q0);
            s1 += t1; q1 = fmaf(t1, t1, q1);
        }
#pragma unroll
        for (int off = 16; off > 0; off >>= 1) {
            s0 += __shfl_xor_sync(0xffffffff, s0, off);
            q0 += __shfl_xor_sync(0xffffffff, q0, off);
            s1 += __shfl_xor_sync(0xffffffff, s1, off);
            q1 += __shfl_xor_sync(0xffffffff, q1, off);
        }
        float mu0 = s0 * (1.f / 256.f);
        float var0 = q0 * (1.f / 256.f) - mu0 * mu0;
        float rs0 = rsqrtf(var0 + EPS);
        float mu1 = s1 * (1.f / 256.f);
        float var1 = q1 * (1.f / 256.f) - mu1 * mu1;
        float rs1 = rsqrtf(var1 + EPS);
        __half2* orow = g_xembh + ((long)b * 128 + c2) * 256;
#pragma unroll
        for (int i = 0; i < 8; i++) {
            int d = lane + i * 32;
            float o0 = (v0[i] - mu0) * rs0 * slw[d] + slb[d];
            float o1 = (v1[i] - mu1) * rs1 * slw[d] + slb[d];
            orow[d] = __floats2half2_rn(o0, o1);
        }
    } else {
        float* s8a = sbuf;
        float* s8b = sbuf + 8;
        int blk = blockIdx.x - 4096;   // 0..511
        int d = tid;
        if (blk < 256) {
            int p = blk;
            float v = embp[p * N256 + d];
            float a = v, bq = v * v;
            block_sum2_256(a, bq, s8a, s8b);
            float mu = a * (1.f / 256.f);
            float var = bq * (1.f / 256.f) - mu * mu;
            float rstd = rsqrtf(var + EPS);
            g_xpin[p * 512 + d] = (v - mu) * rstd * lnpw[d] + lnpb[d];
            g_xpin[p * 512 + 256 + d] = prev[p * N256 + d];
        } else {
            int c = blk - 256;
            float v = embc[c * N256 + d];
            float a = v, bq = v * v;
            block_sum2_256(a, bq, s8a, s8b);
            float mu = a * (1.f / 256.f);
            float var = bq * (1.f / 256.f) - mu * mu;
            float rstd = rsqrtf(var + EPS);
            g_xcol[c * N256 + d] = (v - mu) * rstd * lncw[d] + lncb[d];
        }
    }
}

// ---------------- K2: x_prompt = xp_in @ W^T + b + emb_prompt ---------------
__global__ void xprompt_kernel(const float* __restrict__ W,
                               const float* __restrict__ bias,
                               const float* __restrict__ embp) {
    __shared__ float As[32][17];
    __shared__ float Ws[32][17];
    int tx = threadIdx.x, ty = threadIdx.y;
    int t = ty * 16 + tx;
    int p0 = blockIdx.y * 32;
    int d0 = blockIdx.x * 32;
    float acc[2][2] = {{0.f, 0.f}, {0.f, 0.f}};
    for (int kt = 0; kt < 32; kt++) {
        int k0 = kt * 16;
#pragma unroll
        for (int i = 0; i < 2; i++) {
            int idx = i * 256 + t;
            int r = idx >> 4, k = idx & 15;
            As[r][k] = g_xpin[(p0 + r) * 512 + k0 + k];
            Ws[r][k] = W[(d0 + r) * 512 + k0 + k];
        }
        __syncthreads();
#pragma unroll
        for (int kk = 0; kk < 16; kk++) {
            float a0 = As[ty * 2][kk], a1 = As[ty * 2 + 1][kk];
            float b0 = Ws[tx * 2][kk], b1 = Ws[tx * 2 + 1][kk];
            acc[0][0] += a0 * b0; acc[0][1] += a0 * b1;
            acc[1][0] += a1 * b0; acc[1][1] += a1 * b1;
        }
        __syncthreads();
    }
#pragma unroll
    for (int i = 0; i < 2; i++)
#pragma unroll
        for (int j = 0; j < 2; j++) {
            int p = p0 + ty * 2 + i, dd = d0 + tx * 2 + j;
            g_xprompt[p * N256 + dd] = acc[i][j] + bias[dd] + embp[p * N256 + dd];
        }
}

// ---------------- K3: logits = x_prompt @ x_col^T ---------------------------
__global__ void logits_kernel() {
    __shared__ float As[32][17];
    __shared__ float Bs[32][17];
    int tx = threadIdx.x, ty = threadIdx.y;
    int t = ty * 16 + tx;
    int p0 = blockIdx.y * 32;
    int c0 = blockIdx.x * 32;
    float acc[2][2] = {{0.f, 0.f}, {0.f, 0.f}};
    for (int kt = 0; kt < 16; kt++) {
        int k0 = kt * 16;
#pragma unroll
        for (int i = 0; i < 2; i++) {
            int idx = i * 256 + t;
            int r = idx >> 4, k = idx & 15;
            As[r][k] = g_xprompt[(p0 + r) * N256 + k0 + k];
            Bs[r][k] = g_xcol[(c0 + r) * N256 + k0 + k];
        }
        __syncthreads();
#pragma unroll
        for (int kk = 0; kk < 16; kk++) {
            float a0 = As[ty * 2][kk], a1 = As[ty * 2 + 1][kk];
            float b0 = Bs[tx * 2][kk], b1 = Bs[tx * 2 + 1][kk];
            acc[0][0] += a0 * b0; acc[0][1] += a0 * b1;
            acc[1][0] += a1 * b0; acc[1][1] += a1 * b1;
        }
        __syncthreads();
    }
#pragma unroll
    for (int i = 0; i < 2; i++)
#pragma unroll
        for (int j = 0; j < 2; j++)
            g_logits[(p0 + ty * 2 + i) * N256 + c0 + tx * 2 + j] = acc[i][j];
}

// ---------------- K4: row softmax -> half2-packed mask + fp32 row copy ------
__global__ void softmax_kernel() {
    __shared__ float sw[8];
    int p = blockIdx.x, c = threadIdx.x;
    int lane = c & 31, wid = c >> 5;
    float v = g_logits[p * N256 + c];
    float m = v;
#pragma unroll
    for (int off = 16; off > 0; off >>= 1)
        m = fmaxf(m, __shfl_xor_sync(0xffffffff, m, off));
    if (lane == 0) sw[wid] = m;
    __syncthreads();
    float mx = sw[0];
#pragma unroll
    for (int i = 1; i < 8; i++) mx = fmaxf(mx, sw[i]);
    float e = expf(v - mx);
    float s = e;
#pragma unroll
    for (int off = 16; off > 0; off >>= 1)
        s += __shfl_xor_sync(0xffffffff, s, off);
    __syncthreads();
    if (lane == 0) sw[wid] = s;
    __syncthreads();
    float sum = sw[0];
#pragma unroll
    for (int i = 1; i < 8; i++) sum += sw[i];
    float r = e / sum;
    // epilogue-side bias uses fp16-rounded mask so it matches the GEMM operand
    float rh = __half2float(__float2half_rn(r));
    g_mask_row[p * N256 + c] = rh;
    float other = __shfl_xor_sync(0xffffffff, r, 1);
    if ((c & 1) == 0)
        g_maskh[p * 128 + (c >> 1)] = __floats2half2_rn(r, other);
}

// ---------------- K5: out[b] = mask @ xemb[b], fp16 mma m16n8k16 ------------
// out[0,b,p,d] = (1+ew[p]) * sum_c mask[p,c]*xemb[b,c,d] + mask[b,p]*eb[b]
// Block tile 128x128, K-chunk 32 (16 half2 rows), double-buffered cp.async.
__device__ __forceinline__ void mma_f16(float c[4],
                                        uint32_t a0, uint32_t a1, uint32_t a2, uint32_t a3,
                                        uint32_t b0, uint32_t b1) {
    asm volatile(
        "mma.sync.aligned.m16n8k16.row.col.f32.f16.f16.f32 "
        "{%0,%1,%2,%3}, {%4,%5,%6,%7}, {%8,%9}, {%0,%1,%2,%3};"
        : "+f"(c[0]), "+f"(c[1]), "+f"(c[2]), "+f"(c[3])
        : "r"(a0), "r"(a1), "r"(a2), "r"(a3), "r"(b0), "r"(b1));
}

#define AS_STRIDE 20    // uint32: 16 + 4 pad  -> A-frag reads conflict-free
#define BS_STRIDE 136   // uint32: 128 + 8 pad -> B-frag reads conflict-free

__global__ __launch_bounds__(256, 2) void out_gemm_kernel(
    const float* __restrict__ ew,
    const float* __restrict__ eb,
    float* __restrict__ out) {
    __shared__ __align__(16) uint32_t As2[2][128 * AS_STRIDE];
    __shared__ __align__(16) uint32_t Bs2[2][16 * BS_STRIDE];

    int b = blockIdx.z;
    int m0 = blockIdx.y * 128;
    int n0 = blockIdx.x * 128;
    const uint32_t* A = (const uint32_t*)g_maskh;                   // [256][128]
    const uint32_t* B = (const uint32_t*)(g_xembh + (long)b * 32768); // [128][256]

    int tid = threadIdx.x;
    int lane = tid & 31;
    int warp = tid >> 5;
    int wm = (warp & 1) * 64;
    int wn = (warp >> 1) * 32;
    int grp = lane >> 2;      // 0..7
    int tig = lane & 3;       // 0..3

    float acc[4][4][4];
#pragma unroll
    for (int i = 0; i < 4; i++)
#pragma unroll
        for (int j = 0; j < 4; j++)
#pragma unroll
            for (int k = 0; k < 4; k++) acc[i][j][k] = 0.0f;

    // chunk kt covers c-pairs kp0 = kt*16 .. +15 (k = kt*32 .. +31)
    auto load_tiles = [&](int buf, int kt) {
        int kp0 = kt * 16;
        // A: 128 rows x 16 uint32 = 512 float4 -> 2/thread
#pragma unroll
        for (int t = 0; t < 2; t++) {
            int idx = t * 256 + tid;
            int r = idx >> 2;
            int kc = (idx & 3) << 2;
            cp_async16(&As2[buf][r * AS_STRIDE + kc],
                       A + (m0 + r) * 128 + kp0 + kc);
        }
        // B: 16 rows x 128 uint32 = 512 float4 -> 2/thread
#pragma unroll
        for (int t = 0; t < 2; t++) {
            int idx = t * 256 + tid;
            int r = idx >> 5;
            int nc = (idx & 31) << 2;
            cp_async16(&Bs2[buf][r * BS_STRIDE + nc],
                       B + (kp0 + r) * 256 + n0 + nc);
        }
        cp_commit();
    };

    load_tiles(0, 0);

    for (int kt = 0; kt < 8; kt++) {
        int buf = kt & 1;
        if (kt < 7) {
            load_tiles(buf ^ 1, kt + 1);
            cp_wait<1>();
        } else {
            cp_wait<0>();
        }
        __syncthreads();

        const uint32_t* as = As2[buf];
        const uint32_t* bs = Bs2[buf];
#pragma unroll
        for (int ks = 0; ks < 2; ks++) {
            int kk2 = ks * 8;          // half2-row base within chunk
            uint32_t afr[4][4];
#pragma unroll
            for (int mi = 0; mi < 4; mi++) {
                int rb = wm + mi * 16 + grp;
                afr[mi][0] = as[rb * AS_STRIDE + kk2 + tig];
                afr[mi][1] = as[(rb + 8) * AS_STRIDE + kk2 + tig];
                afr[mi][2] = as[rb * AS_STRIDE + kk2 + tig + 4];
                afr[mi][3] = as[(rb + 8) * AS_STRIDE + kk2 + tig + 4];
            }
            uint32_t bfr[4][2];
#pragma unroll
            for (int ni = 0; ni < 4; ni++) {
                int nb = wn + ni * 8 + grp;
                bfr[ni][0] = bs[(kk2 + tig) * BS_STRIDE + nb];
                bfr[ni][1] = bs[(kk2 + tig + 4) * BS_STRIDE + nb];
            }
#pragma unroll
            for (int mi = 0; mi < 4; mi++)
#pragma unroll
                for (int ni = 0; ni < 4; ni++)
                    mma_f16(acc[mi][ni],
                            afr[mi][0], afr[mi][1], afr[mi][2], afr[mi][3],
                            bfr[ni][0], bfr[ni][1]);
        }
        __syncthreads();
    }

    // epilogue: scale by (1+ew[p]) and add mask[b,p]*eb[b]
    const float* maskb = g_mask_row + b * 256;
    float ebb = eb[b];
#pragma unroll
    for (int mi = 0; mi < 4; mi++) {
#pragma unroll
        for (int h = 0; h < 2; h++) {
            int p = m0 + wm + mi * 16 + grp + h * 8;
            float scale = 1.0f + ew[p];
            float addv = maskb[p] * ebb;
            long rowoff = ((long)(b * 256 + p)) * 256;
#pragma unroll
            for (int ni = 0; ni < 4; ni++) {
                int d = n0 + wn + ni * 8 + tig * 2;
                float v0 = acc[mi][ni][h * 2 + 0] * scale + addv;
                float v1 = acc[mi][ni][h * 2 + 1] * scale + addv;
                *(float2*)(out + rowoff + d) = make_float2(v0, v1);
            }
        }
    }
}

// ---------------- launch -----------------------------------------------------
extern "C" void kernel_launch(void* const* d_in, const int* in_sizes, int n_in,
                              void* d_out, int out_size) {
    const float* x    = (const float*)d_in[0];
    const float* prev = (const float*)d_in[1];
    const float* few  = (const float*)d_in[2];
    const float* feb  = (const float*)d_in[3];
    const float* lnew = (const float*)d_in[4];
    const float* lneb = (const float*)d_in[5];
    const float* lncw = (const float*)d_in[6];
    const float* lncb = (const float*)d_in[7];
    const float* lnpw = (const float*)d_in[8];
    const float* lnpb = (const float*)d_in[9];
    const float* diw  = (const float*)d_in[10];
    const float* dib  = (const float*)d_in[11];
    const float* embc = (const float*)d_in[12];
    const float* embp = (const float*)d_in[13];
    const float* ew   = (const float*)d_in[14];
    const float* ebia = (const float*)d_in[15];
    float* out = (float*)d_out;

    xemb_prep_kernel<<<4608, 256>>>(x, few, feb, lnew, lneb,
                                    embp, lnpw, lnpb, prev, embc, lncw, lncb);
    xprompt_kernel<<<dim3(8, 8), dim3(16, 16)>>>(diw, dib, embp);
    logits_kernel<<<dim3(8, 8), dim3(16, 16)>>>();
    softmax_kernel<<<256, 256>>>();
    out_gemm_kernel<<<dim3(2, 2, 256), 256>>>(ew, ebia, out);
}

// round 8
// speedup vs baseline: 2.0785x; 1.0444x over previous
#include <cuda_runtime.h>
#include <cuda_fp16.h>
#include <cstdint>

// Problem constants: B=C=P=D=256
#define N256 256
#define EPS 1e-5f

// ---------------- scratch (device globals; no allocations allowed) ----------
__device__ __half2 g_xembh[256 * 128 * 256]; // [b][c/2][d] k-pair-packed halves
__device__ __half2 g_maskh[256 * 128];       // [p][c/2] k-pair-packed halves
__device__ float g_xprompt[256 * 256];       // [P,D]
__device__ float g_xcol[256 * 256];          // [C,D] LN(emb_column)
__device__ float g_xpin[256 * 512];          // [P,2D]
__device__ float g_logits[256 * 256];        // [P,C]

// ---------------- helpers ----------------------------------------------------
__device__ __forceinline__ void cp_async16(void* smem, const void* gmem) {
    uint32_t s = (uint32_t)__cvta_generic_to_shared(smem);
    asm volatile("cp.async.cg.shared.global [%0], [%1], 16;" :: "r"(s), "l"(gmem));
}
__device__ __forceinline__ void cp_commit() {
    asm volatile("cp.async.commit_group;" ::: "memory");
}
template <int N>
__device__ __forceinline__ void cp_wait() {
    asm volatile("cp.async.wait_group %0;" :: "n"(N) : "memory");
}
__device__ __forceinline__ void ldsm_x4(uint32_t& r0, uint32_t& r1,
                                        uint32_t& r2, uint32_t& r3,
                                        const void* smem_ptr) {
    uint32_t a = (uint32_t)__cvta_generic_to_shared(smem_ptr);
    asm volatile("ldmatrix.sync.aligned.m8n8.x4.shared.b16 {%0,%1,%2,%3}, [%4];"
                 : "=r"(r0), "=r"(r1), "=r"(r2), "=r"(r3) : "r"(a));
}

// dual warp+block reduce
__device__ __forceinline__ void block_sum2_256(float& a, float& b,
                                               float* s8a, float* s8b) {
    int lane = threadIdx.x & 31, wid = threadIdx.x >> 5;
#pragma unroll
    for (int off = 16; off > 0; off >>= 1) {
        a += __shfl_xor_sync(0xffffffff, a, off);
        b += __shfl_xor_sync(0xffffffff, b, off);
    }
    if (lane == 0) { s8a[wid] = a; s8b[wid] = b; }
    __syncthreads();
    a = s8a[0]; b = s8b[0];
#pragma unroll
    for (int i = 1; i < 8; i++) { a += s8a[i]; b += s8b[i]; }
}

// ---------------- K1: xemb pairs (blocks 0..4095) + prep (4096..4607) -------
__global__ void xemb_prep_kernel(const float* __restrict__ x,
                                 const float* __restrict__ few,
                                 const float* __restrict__ feb,
                                 const float* __restrict__ lnew,
                                 const float* __restrict__ lneb,
                                 const float* __restrict__ embp,
                                 const float* __restrict__ lnpw,
                                 const float* __restrict__ lnpb,
                                 const float* __restrict__ prev,
                                 const float* __restrict__ embc,
                                 const float* __restrict__ lncw,
                                 const float* __restrict__ lncb) {
    __shared__ float sbuf[6 * 256 + 16];
    int tid = threadIdx.x;
    if (blockIdx.x < 4096) {
        float* sw0 = sbuf;
        float* sb0 = sbuf + 256;
        float* sw1 = sbuf + 512;
        float* sb1 = sbuf + 768;
        float* slw = sbuf + 1024;
        float* slb = sbuf + 1280;
        int c2 = blockIdx.x >> 5;
        int bg = blockIdx.x & 31;
        int c0 = c2 * 2, c1 = c0 + 1;
        sw0[tid] = few[c0 * 256 + tid];
        sb0[tid] = feb[c0 * 256 + tid];
        sw1[tid] = few[c1 * 256 + tid];
        sb1[tid] = feb[c1 * 256 + tid];
        slw[tid] = lnew[tid];
        slb[tid] = lneb[tid];
        __syncthreads();

        int lane = tid & 31;
        int wid = tid >> 5;
        int b = bg * 8 + wid;
        float xv0 = x[b * 256 + c0];
        float xv1 = x[b * 256 + c1];
        float v0[8], v1[8];
        float s0 = 0.f, q0 = 0.f, s1 = 0.f, q1 = 0.f;
#pragma unroll
        for (int i = 0; i < 8; i++) {
            int d = lane + i * 32;
            float t0 = fmaf(xv0, sw0[d], sb0[d]);
            float t1 = fmaf(xv1, sw1[d], sb1[d]);
            t0 = t0 > 0.f ? t0 : 0.f;
            t1 = t1 > 0.f ? t1 : 0.f;
            v0[i] = t0; v1[i] = t1;
            s0 += t0; q0 = fmaf(t0, t0, q0);
            s1 += t1; q1 = fmaf(t1, t1, q1);
        }
#pragma unroll
        for (int off = 16; off > 0; off >>= 1) {
            s0 += __shfl_xor_sync(0xffffffff, s0, off);
            q0 += __shfl_xor_sync(0xffffffff, q0, off);
            s1 += __shfl_xor_sync(0xffffffff, s1, off);
            q1 += __shfl_xor_sync(0xffffffff, q1, off);
        }
        float mu0 = s0 * (1.f / 256.f);
        float rs0 = rsqrtf(q0 * (1.f / 256.f) - mu0 * mu0 + EPS);
        float mu1 = s1 * (1.f / 256.f);
        float rs1 = rsqrtf(q1 * (1.f / 256.f) - mu1 * mu1 + EPS);
        __half2* orow = g_xembh + ((long)b * 128 + c2) * 256;
#pragma unroll
        for (int i = 0; i < 8; i++) {
            int d = lane + i * 32;
            float o0 = (v0[i] - mu0) * rs0 * slw[d] + slb[d];
            float o1 = (v1[i] - mu1) * rs1 * slw[d] + slb[d];
            orow[d] = __floats2half2_rn(o0, o1);
        }
    } else {
        float* s8a = sbuf;
        float* s8b = sbuf + 8;
        int blk = blockIdx.x - 4096;
        int d = tid;
        if (blk < 256) {
            int p = blk;
            float v = embp[p * N256 + d];
            float a = v, bq = v * v;
            block_sum2_256(a, bq, s8a, s8b);
            float mu = a * (1.f / 256.f);
            float rstd = rsqrtf(bq * (1.f / 256.f) - mu * mu + EPS);
            g_xpin[p * 512 + d] = (v - mu) * rstd * lnpw[d] + lnpb[d];
            g_xpin[p * 512 + 256 + d] = prev[p * N256 + d];
        } else {
            int c = blk - 256;
            float v = embc[c * N256 + d];
            float a = v, bq = v * v;
            block_sum2_256(a, bq, s8a, s8b);
            float mu = a * (1.f / 256.f);
            float rstd = rsqrtf(bq * (1.f / 256.f) - mu * mu + EPS);
            g_xcol[c * N256 + d] = (v - mu) * rstd * lncw[d] + lncb[d];
        }
    }
}

// ---------------- K2: x_prompt = xp_in @ W^T + b + emb_prompt ---------------
__global__ void xprompt_kernel(const float* __restrict__ W,
                               const float* __restrict__ bias,
                               const float* __restrict__ embp) {
    __shared__ float As[32][17];
    __shared__ float Ws[32][17];
    int tx = threadIdx.x, ty = threadIdx.y;
    int t = ty * 16 + tx;
    int p0 = blockIdx.y * 32;
    int d0 = blockIdx.x * 32;
    float acc[2][2] = {{0.f, 0.f}, {0.f, 0.f}};
    for (int kt = 0; kt < 32; kt++) {
        int k0 = kt * 16;
#pragma unroll
        for (int i = 0; i < 2; i++) {
            int idx = i * 256 + t;
            int r = idx >> 4, k = idx & 15;
            As[r][k] = g_xpin[(p0 + r) * 512 + k0 + k];
            Ws[r][k] = W[(d0 + r) * 512 + k0 + k];
        }
        __syncthreads();
#pragma unroll
        for (int kk = 0; kk < 16; kk++) {
            float a0 = As[ty * 2][kk], a1 = As[ty * 2 + 1][kk];
            float b0 = Ws[tx * 2][kk], b1 = Ws[tx * 2 + 1][kk];
            acc[0][0] += a0 * b0; acc[0][1] += a0 * b1;
            acc[1][0] += a1 * b0; acc[1][1] += a1 * b1;
        }
        __syncthreads();
    }
#pragma unroll
    for (int i = 0; i < 2; i++)
#pragma unroll
        for (int j = 0; j < 2; j++) {
            int p = p0 + ty * 2 + i, dd = d0 + tx * 2 + j;
            g_xprompt[p * N256 + dd] = acc[i][j] + bias[dd] + embp[p * N256 + dd];
        }
}

// ---------------- K3: logits = x_prompt @ x_col^T ---------------------------
__global__ void logits_kernel() {
    __shared__ float As[32][17];
    __shared__ float Bs[32][17];
    int tx = threadIdx.x, ty = threadIdx.y;
    int t = ty * 16 + tx;
    int p0 = blockIdx.y * 32;
    int c0 = blockIdx.x * 32;
    float acc[2][2] = {{0.f, 0.f}, {0.f, 0.f}};
    for (int kt = 0; kt < 16; kt++) {
        int k0 = kt * 16;
#pragma unroll
        for (int i = 0; i < 2; i++) {
            int idx = i * 256 + t;
            int r = idx >> 4, k = idx & 15;
            As[r][k] = g_xprompt[(p0 + r) * N256 + k0 + k];
            Bs[r][k] = g_xcol[(c0 + r) * N256 + k0 + k];
        }
        __syncthreads();
#pragma unroll
        for (int kk = 0; kk < 16; kk++) {
            float a0 = As[ty * 2][kk], a1 = As[ty * 2 + 1][kk];
            float b0 = Bs[tx * 2][kk], b1 = Bs[tx * 2 + 1][kk];
            acc[0][0] += a0 * b0; acc[0][1] += a0 * b1;
            acc[1][0] += a1 * b0; acc[1][1] += a1 * b1;
        }
        __syncthreads();
    }
#pragma unroll
    for (int i = 0; i < 2; i++)
#pragma unroll
        for (int j = 0; j < 2; j++)
            g_logits[(p0 + ty * 2 + i) * N256 + c0 + tx * 2 + j] = acc[i][j];
}

// ---------------- K4: warp-per-row softmax -> half2-packed mask -------------
// 8 warps/block, each warp owns one p-row; no block-level syncs.
__global__ void softmax_kernel() {
    int lane = threadIdx.x & 31;
    int wid = threadIdx.x >> 5;
    int p = blockIdx.x * 8 + wid;
    const float* row = g_logits + p * N256;
    float4 v0 = *(const float4*)(row + lane * 4);
    float4 v1 = *(const float4*)(row + 128 + lane * 4);
    float m = fmaxf(fmaxf(fmaxf(v0.x, v0.y), fmaxf(v0.z, v0.w)),
                    fmaxf(fmaxf(v1.x, v1.y), fmaxf(v1.z, v1.w)));
#pragma unroll
    for (int off = 16; off > 0; off >>= 1)
        m = fmaxf(m, __shfl_xor_sync(0xffffffff, m, off));
    float e0 = expf(v0.x - m), e1 = expf(v0.y - m);
    float e2 = expf(v0.z - m), e3 = expf(v0.w - m);
    float f0 = expf(v1.x - m), f1 = expf(v1.y - m);
    float f2 = expf(v1.z - m), f3 = expf(v1.w - m);
    float s = e0 + e1 + e2 + e3 + f0 + f1 + f2 + f3;
#pragma unroll
    for (int off = 16; off > 0; off >>= 1)
        s += __shfl_xor_sync(0xffffffff, s, off);
    float inv = 1.0f / s;
    __half2* mrow = g_maskh + p * 128;
    mrow[lane * 2 + 0] = __floats2half2_rn(e0 * inv, e1 * inv);
    mrow[lane * 2 + 1] = __floats2half2_rn(e2 * inv, e3 * inv);
    mrow[64 + lane * 2 + 0] = __floats2half2_rn(f0 * inv, f1 * inv);
    mrow[64 + lane * 2 + 1] = __floats2half2_rn(f2 * inv, f3 * inv);
}

// ---------------- K5: out[b] = mask @ xemb[b], fp16 mma m16n8k16 ------------
__device__ __forceinline__ void mma_f16(float c[4],
                                        uint32_t a0, uint32_t a1, uint32_t a2, uint32_t a3,
                                        uint32_t b0, uint32_t b1) {
    asm volatile(
        "mma.sync.aligned.m16n8k16.row.col.f32.f16.f16.f32 "
        "{%0,%1,%2,%3}, {%4,%5,%6,%7}, {%8,%9}, {%0,%1,%2,%3};"
        : "+f"(c[0]), "+f"(c[1]), "+f"(c[2]), "+f"(c[3])
        : "r"(a0), "r"(a1), "r"(a2), "r"(a3), "r"(b0), "r"(b1));
}

#define AS_STRIDE 20    // uint32: 16 + 4 pad  -> ldmatrix rows hit distinct banks
#define BS_STRIDE 136   // uint32: 128 + 8 pad -> B-frag reads conflict-free

__global__ __launch_bounds__(256, 2) void out_gemm_kernel(
    const float* __restrict__ ew,
    const float* __restrict__ eb,
    float* __restrict__ out) {
    __shared__ __align__(16) uint32_t As2[2][128 * AS_STRIDE];
    __shared__ __align__(16) uint32_t Bs2[2][16 * BS_STRIDE];

    int b = blockIdx.z;
    int m0 = blockIdx.y * 128;
    int n0 = blockIdx.x * 128;
    const uint32_t* A = (const uint32_t*)g_maskh;                     // [256][128]
    const uint32_t* B = (const uint32_t*)(g_xembh + (long)b * 32768); // [128][256]

    int tid = threadIdx.x;
    int lane = tid & 31;
    int warp = tid >> 5;
    int wm = (warp & 1) * 64;
    int wn = (warp >> 1) * 32;
    int grp = lane >> 2;      // 0..7
    int tig = lane & 3;       // 0..3

    // ldmatrix lane addressing: matrix idx = lane>>3, row-in-matrix = lane&7
    int lrow = lane & 7;
    int lm = lane >> 3;
    int lds_row_off = lrow + ((lm & 1) << 3);   // +8 rows for matrices 1,3
    int lds_col_off = (lm >> 1) << 2;           // +4 u32 (k+8) for matrices 2,3

    float acc[4][4][4];
#pragma unroll
    for (int i = 0; i < 4; i++)
#pragma unroll
        for (int j = 0; j < 4; j++)
#pragma unroll
            for (int k = 0; k < 4; k++) acc[i][j][k] = 0.0f;

    auto load_tiles = [&](int buf, int kt) {
        int kp0 = kt * 16;
#pragma unroll
        for (int t = 0; t < 2; t++) {
            int idx = t * 256 + tid;
            int r = idx >> 2;
            int kc = (idx & 3) << 2;
            cp_async16(&As2[buf][r * AS_STRIDE + kc],
                       A + (m0 + r) * 128 + kp0 + kc);
        }
#pragma unroll
        for (int t = 0; t < 2; t++) {
            int idx = t * 256 + tid;
            int r = idx >> 5;
            int nc = (idx & 31) << 2;
            cp_async16(&Bs2[buf][r * BS_STRIDE + nc],
                       B + (kp0 + r) * 256 + n0 + nc);
        }
        cp_commit();
    };

    load_tiles(0, 0);

    for (int kt = 0; kt < 8; kt++) {
        int buf = kt & 1;
        if (kt < 7) {
            load_tiles(buf ^ 1, kt + 1);
            cp_wait<1>();
        } else {
            cp_wait<0>();
        }
        __syncthreads();

        const uint32_t* as = As2[buf];
        const uint32_t* bs = Bs2[buf];
#pragma unroll
        for (int ks = 0; ks < 2; ks++) {
            int kk2 = ks * 8;
            uint32_t afr[4][4];
#pragma unroll
            for (int mi = 0; mi < 4; mi++) {
                int rb = wm + mi * 16 + lds_row_off;
                ldsm_x4(afr[mi][0], afr[mi][1], afr[mi][2], afr[mi][3],
                        &as[rb * AS_STRIDE + kk2 + lds_col_off]);
            }
            uint32_t bfr[4][2];
#pragma unroll
            for (int ni = 0; ni < 4; ni++) {
                int nb = wn + ni * 8 + grp;
                bfr[ni][0] = bs[(kk2 + tig) * BS_STRIDE + nb];
                bfr[ni][1] = bs[(kk2 + tig + 4) * BS_STRIDE + nb];
            }
#pragma unroll
            for (int mi = 0; mi < 4; mi++)
#pragma unroll
                for (int ni = 0; ni < 4; ni++)
                    mma_f16(acc[mi][ni],
                            afr[mi][0], afr[mi][1], afr[mi][2], afr[mi][3],
                            bfr[ni][0], bfr[ni][1]);
        }
        __syncthreads();
    }

    // epilogue: scale by (1+ew[p]) and add mask[b,p]*eb[b] (fp16 mask value)
    const __half2* maskb = g_maskh + b * 128;
    float ebb = eb[b];
#pragma unroll
    for (int mi = 0; mi < 4; mi++) {
#pragma unroll
        for (int h = 0; h < 2; h++) {
            int p = m0 + wm + mi * 16 + grp + h * 8;
            float scale = 1.0f + ew[p];
            __half2 mh = maskb[p >> 1];
            float mval = (p & 1) ? __high2float(mh) : __low2float(mh);
            float addv = mval * ebb;
            long rowoff = ((long)(b * 256 + p)) * 256;
#pragma unroll
            for (int ni = 0; ni < 4; ni++) {
                int d = n0 + wn + ni * 8 + tig * 2;
                float v0 = acc[mi][ni][h * 2 + 0] * scale + addv;
                float v1 = acc[mi][ni][h * 2 + 1] * scale + addv;
                *(float2*)(out + rowoff + d) = make_float2(v0, v1);
            }
        }
    }
}

// ---------------- launch -----------------------------------------------------
extern "C" void kernel_launch(void* const* d_in, const int* in_sizes, int n_in,
                              void* d_out, int out_size) {
    const float* x    = (const float*)d_in[0];
    const float* prev = (const float*)d_in[1];
    const float* few  = (const float*)d_in[2];
    const float* feb  = (const float*)d_in[3];
    const float* lnew = (const float*)d_in[4];
    const float* lneb = (const float*)d_in[5];
    const float* lncw = (const float*)d_in[6];
    const float* lncb = (const float*)d_in[7];
    const float* lnpw = (const float*)d_in[8];
    const float* lnpb = (const float*)d_in[9];
    const float* diw  = (const float*)d_in[10];
    const float* dib  = (const float*)d_in[11];
    const float* embc = (const float*)d_in[12];
    const float* embp = (const float*)d_in[13];
    const float* ew   = (const float*)d_in[14];
    const float* ebia = (const float*)d_in[15];
    float* out = (float*)d_out;

    xemb_prep_kernel<<<4608, 256>>>(x, few, feb, lnew, lneb,
                                    embp, lnpw, lnpb, prev, embc, lncw, lncb);
    xprompt_kernel<<<dim3(8, 8), dim3(16, 16)>>>(diw, dib, embp);
    logits_kernel<<<dim3(8, 8), dim3(16, 16)>>>();
    softmax_kernel<<<32, 256>>>();
    out_gemm_kernel<<<dim3(2, 2, 256), 256>>>(ew, ebia, out);
}

// round 9
// speedup vs baseline: 2.1411x; 1.0301x over previous
#include <cuda_runtime.h>
#include <cuda_fp16.h>
#include <cstdint>

// Problem constants: B=C=P=D=256
#define N256 256
#define EPS 1e-5f

// ---------------- scratch (device globals; no allocations allowed) ----------
__device__ __half2 g_xembh[256 * 128 * 256]; // [b][c/2][d] k-pair-packed halves
__device__ __half2 g_maskh[256 * 128];       // [p][c/2] k-pair-packed halves
__device__ float g_xprompt[256 * 256];       // [P,D]
__device__ float g_xcol[256 * 256];          // [C,D] LN(emb_column)
__device__ float g_xpin[256 * 512];          // [P,2D]
__device__ float g_logits[256 * 256];        // [P,C]

// ---------------- helpers ----------------------------------------------------
__device__ __forceinline__ void cp_async16(void* smem, const void* gmem) {
    uint32_t s = (uint32_t)__cvta_generic_to_shared(smem);
    asm volatile("cp.async.cg.shared.global [%0], [%1], 16;" :: "r"(s), "l"(gmem));
}
__device__ __forceinline__ void cp_commit() {
    asm volatile("cp.async.commit_group;" ::: "memory");
}
template <int N>
__device__ __forceinline__ void cp_wait() {
    asm volatile("cp.async.wait_group %0;" :: "n"(N) : "memory");
}
__device__ __forceinline__ void ldsm_x4(uint32_t& r0, uint32_t& r1,
                                        uint32_t& r2, uint32_t& r3,
                                        const void* smem_ptr) {
    uint32_t a = (uint32_t)__cvta_generic_to_shared(smem_ptr);
    asm volatile("ldmatrix.sync.aligned.m8n8.x4.shared.b16 {%0,%1,%2,%3}, [%4];"
                 : "=r"(r0), "=r"(r1), "=r"(r2), "=r"(r3) : "r"(a));
}

// dual warp+block reduce
__device__ __forceinline__ void block_sum2_256(float& a, float& b,
                                               float* s8a, float* s8b) {
    int lane = threadIdx.x & 31, wid = threadIdx.x >> 5;
#pragma unroll
    for (int off = 16; off > 0; off >>= 1) {
        a += __shfl_xor_sync(0xffffffff, a, off);
        b += __shfl_xor_sync(0xffffffff, b, off);
    }
    if (lane == 0) { s8a[wid] = a; s8b[wid] = b; }
    __syncthreads();
    a = s8a[0]; b = s8b[0];
#pragma unroll
    for (int i = 1; i < 8; i++) { a += s8a[i]; b += s8b[i]; }
}

// ---------------- K1: xemb pairs (blocks 0..4095) + prep (4096..4607) -------
__global__ void xemb_prep_kernel(const float* __restrict__ x,
                                 const float* __restrict__ few,
                                 const float* __restrict__ feb,
                                 const float* __restrict__ lnew,
                                 const float* __restrict__ lneb,
                                 const float* __restrict__ embp,
                                 const float* __restrict__ lnpw,
                                 const float* __restrict__ lnpb,
                                 const float* __restrict__ prev,
                                 const float* __restrict__ embc,
                                 const float* __restrict__ lncw,
                                 const float* __restrict__ lncb) {
    __shared__ float sbuf[6 * 256 + 16];
    int tid = threadIdx.x;
    if (blockIdx.x < 4096) {
        float* sw0 = sbuf;
        float* sb0 = sbuf + 256;
        float* sw1 = sbuf + 512;
        float* sb1 = sbuf + 768;
        float* slw = sbuf + 1024;
        float* slb = sbuf + 1280;
        int c2 = blockIdx.x >> 5;
        int bg = blockIdx.x & 31;
        int c0 = c2 * 2, c1 = c0 + 1;
        sw0[tid] = few[c0 * 256 + tid];
        sb0[tid] = feb[c0 * 256 + tid];
        sw1[tid] = few[c1 * 256 + tid];
        sb1[tid] = feb[c1 * 256 + tid];
        slw[tid] = lnew[tid];
        slb[tid] = lneb[tid];
        __syncthreads();

        int lane = tid & 31;
        int wid = tid >> 5;
        int b = bg * 8 + wid;
        float xv0 = x[b * 256 + c0];
        float xv1 = x[b * 256 + c1];
        float v0[8], v1[8];
        float s0 = 0.f, q0 = 0.f, s1 = 0.f, q1 = 0.f;
#pragma unroll
        for (int i = 0; i < 8; i++) {
            int d = lane + i * 32;
            float t0 = fmaf(xv0, sw0[d], sb0[d]);
            float t1 = fmaf(xv1, sw1[d], sb1[d]);
            t0 = t0 > 0.f ? t0 : 0.f;
            t1 = t1 > 0.f ? t1 : 0.f;
            v0[i] = t0; v1[i] = t1;
            s0 += t0; q0 = fmaf(t0, t0, q0);
            s1 += t1; q1 = fmaf(t1, t1, q1);
        }
#pragma unroll
        for (int off = 16; off > 0; off >>= 1) {
            s0 += __shfl_xor_sync(0xffffffff, s0, off);
            q0 += __shfl_xor_sync(0xffffffff, q0, off);
            s1 += __shfl_xor_sync(0xffffffff, s1, off);
            q1 += __shfl_xor_sync(0xffffffff, q1, off);
        }
        float mu0 = s0 * (1.f / 256.f);
        float rs0 = rsqrtf(q0 * (1.f / 256.f) - mu0 * mu0 + EPS);
        float mu1 = s1 * (1.f / 256.f);
        float rs1 = rsqrtf(q1 * (1.f / 256.f) - mu1 * mu1 + EPS);
        __half2* orow = g_xembh + ((long)b * 128 + c2) * 256;
#pragma unroll
        for (int i = 0; i < 8; i++) {
            int d = lane + i * 32;
            float o0 = (v0[i] - mu0) * rs0 * slw[d] + slb[d];
            float o1 = (v1[i] - mu1) * rs1 * slw[d] + slb[d];
            orow[d] = __floats2half2_rn(o0, o1);
        }
    } else {
        float* s8a = sbuf;
        float* s8b = sbuf + 8;
        int blk = blockIdx.x - 4096;
        int d = tid;
        if (blk < 256) {
            int p = blk;
            float v = embp[p * N256 + d];
            float a = v, bq = v * v;
            block_sum2_256(a, bq, s8a, s8b);
            float mu = a * (1.f / 256.f);
            float rstd = rsqrtf(bq * (1.f / 256.f) - mu * mu + EPS);
            g_xpin[p * 512 + d] = (v - mu) * rstd * lnpw[d] + lnpb[d];
            g_xpin[p * 512 + 256 + d] = prev[p * N256 + d];
        } else {
            int c = blk - 256;
            float v = embc[c * N256 + d];
            float a = v, bq = v * v;
            block_sum2_256(a, bq, s8a, s8b);
            float mu = a * (1.f / 256.f);
            float rstd = rsqrtf(bq * (1.f / 256.f) - mu * mu + EPS);
            g_xcol[c * N256 + d] = (v - mu) * rstd * lncw[d] + lncb[d];
        }
    }
}

// ---------------- K2: x_prompt = xp_in @ W^T + b + emb_prompt ---------------
__global__ void xprompt_kernel(const float* __restrict__ W,
                               const float* __restrict__ bias,
                               const float* __restrict__ embp) {
    __shared__ float As[32][17];
    __shared__ float Ws[32][17];
    int tx = threadIdx.x, ty = threadIdx.y;
    int t = ty * 16 + tx;
    int p0 = blockIdx.y * 32;
    int d0 = blockIdx.x * 32;
    float acc[2][2] = {{0.f, 0.f}, {0.f, 0.f}};
    for (int kt = 0; kt < 32; kt++) {
        int k0 = kt * 16;
#pragma unroll
        for (int i = 0; i < 2; i++) {
            int idx = i * 256 + t;
            int r = idx >> 4, k = idx & 15;
            As[r][k] = g_xpin[(p0 + r) * 512 + k0 + k];
            Ws[r][k] = W[(d0 + r) * 512 + k0 + k];
        }
        __syncthreads();
#pragma unroll
        for (int kk = 0; kk < 16; kk++) {
            float a0 = As[ty * 2][kk], a1 = As[ty * 2 + 1][kk];
            float b0 = Ws[tx * 2][kk], b1 = Ws[tx * 2 + 1][kk];
            acc[0][0] += a0 * b0; acc[0][1] += a0 * b1;
            acc[1][0] += a1 * b0; acc[1][1] += a1 * b1;
        }
        __syncthreads();
    }
#pragma unroll
    for (int i = 0; i < 2; i++)
#pragma unroll
        for (int j = 0; j < 2; j++) {
            int p = p0 + ty * 2 + i, dd = d0 + tx * 2 + j;
            g_xprompt[p * N256 + dd] = acc[i][j] + bias[dd] + embp[p * N256 + dd];
        }
}

// ---------------- K3: logits = x_prompt @ x_col^T ---------------------------
__global__ void logits_kernel() {
    __shared__ float As[32][17];
    __shared__ float Bs[32][17];
    int tx = threadIdx.x, ty = threadIdx.y;
    int t = ty * 16 + tx;
    int p0 = blockIdx.y * 32;
    int c0 = blockIdx.x * 32;
    float acc[2][2] = {{0.f, 0.f}, {0.f, 0.f}};
    for (int kt = 0; kt < 16; kt++) {
        int k0 = kt * 16;
#pragma unroll
        for (int i = 0; i < 2; i++) {
            int idx = i * 256 + t;
            int r = idx >> 4, k = idx & 15;
            As[r][k] = g_xprompt[(p0 + r) * N256 + k0 + k];
            Bs[r][k] = g_xcol[(c0 + r) * N256 + k0 + k];
        }
        __syncthreads();
#pragma unroll
        for (int kk = 0; kk < 16; kk++) {
            float a0 = As[ty * 2][kk], a1 = As[ty * 2 + 1][kk];
            float b0 = Bs[tx * 2][kk], b1 = Bs[tx * 2 + 1][kk];
            acc[0][0] += a0 * b0; acc[0][1] += a0 * b1;
            acc[1][0] += a1 * b0; acc[1][1] += a1 * b1;
        }
        __syncthreads();
    }
#pragma unroll
    for (int i = 0; i < 2; i++)
#pragma unroll
        for (int j = 0; j < 2; j++)
            g_logits[(p0 + ty * 2 + i) * N256 + c0 + tx * 2 + j] = acc[i][j];
}

// ---------------- K4: warp-per-row softmax, 256 blocks x 32 threads ----------
__global__ void softmax_kernel() {
    int lane = threadIdx.x;
    int p = blockIdx.x;
    const float* row = g_logits + p * N256;
    float4 v0 = __ldg((const float4*)(row + lane * 4));
    float4 v1 = __ldg((const float4*)(row + 128 + lane * 4));
    float m = fmaxf(fmaxf(fmaxf(v0.x, v0.y), fmaxf(v0.z, v0.w)),
                    fmaxf(fmaxf(v1.x, v1.y), fmaxf(v1.z, v1.w)));
#pragma unroll
    for (int off = 16; off > 0; off >>= 1)
        m = fmaxf(m, __shfl_xor_sync(0xffffffff, m, off));
    float e0 = expf(v0.x - m), e1 = expf(v0.y - m);
    float e2 = expf(v0.z - m), e3 = expf(v0.w - m);
    float f0 = expf(v1.x - m), f1 = expf(v1.y - m);
    float f2 = expf(v1.z - m), f3 = expf(v1.w - m);
    float s = e0 + e1 + e2 + e3 + f0 + f1 + f2 + f3;
#pragma unroll
    for (int off = 16; off > 0; off >>= 1)
        s += __shfl_xor_sync(0xffffffff, s, off);
    float inv = 1.0f / s;
    __half2* mrow = g_maskh + p * 128;
    mrow[lane * 2 + 0] = __floats2half2_rn(e0 * inv, e1 * inv);
    mrow[lane * 2 + 1] = __floats2half2_rn(e2 * inv, e3 * inv);
    mrow[64 + lane * 2 + 0] = __floats2half2_rn(f0 * inv, f1 * inv);
    mrow[64 + lane * 2 + 1] = __floats2half2_rn(f2 * inv, f3 * inv);
}

// ---------------- K5: out[b] = mask @ xemb[b], fp16 mma, 3-stage pipeline ---
__device__ __forceinline__ void mma_f16(float c[4],
                                        uint32_t a0, uint32_t a1, uint32_t a2, uint32_t a3,
                                        uint32_t b0, uint32_t b1) {
    asm volatile(
        "mma.sync.aligned.m16n8k16.row.col.f32.f16.f16.f32 "
        "{%0,%1,%2,%3}, {%4,%5,%6,%7}, {%8,%9}, {%0,%1,%2,%3};"
        : "+f"(c[0]), "+f"(c[1]), "+f"(c[2]), "+f"(c[3])
        : "r"(a0), "r"(a1), "r"(a2), "r"(a3), "r"(b0), "r"(b1));
}

#define AS_STRIDE 20    // uint32: 16 + 4 pad
#define BS_STRIDE 136   // uint32: 128 + 8 pad
#define AS_BUF (128 * AS_STRIDE)
#define BS_BUF (16 * BS_STRIDE)
#define STAGE_U32 (AS_BUF + BS_BUF)
#define GEMM_SMEM_BYTES (3 * STAGE_U32 * 4)   // 56832 B

__global__ __launch_bounds__(256, 2) void out_gemm_kernel(
    const float* __restrict__ ew,
    const float* __restrict__ eb,
    float* __restrict__ out) {
    extern __shared__ __align__(16) uint32_t smem[];
    // stage s: A at smem + s*STAGE_U32, B at smem + s*STAGE_U32 + AS_BUF

    int b = blockIdx.z;
    int m0 = blockIdx.y * 128;
    int n0 = blockIdx.x * 128;
    const uint32_t* A = (const uint32_t*)g_maskh;                     // [256][128]
    const uint32_t* B = (const uint32_t*)(g_xembh + (long)b * 32768); // [128][256]

    int tid = threadIdx.x;
    int lane = tid & 31;
    int warp = tid >> 5;
    int wm = (warp & 1) * 64;
    int wn = (warp >> 1) * 32;
    int grp = lane >> 2;
    int tig = lane & 3;

    int lrow = lane & 7;
    int lm = lane >> 3;
    int lds_row_off = lrow + ((lm & 1) << 3);
    int lds_col_off = (lm >> 1) << 2;

    float acc[4][4][4];
#pragma unroll
    for (int i = 0; i < 4; i++)
#pragma unroll
        for (int j = 0; j < 4; j++)
#pragma unroll
            for (int k = 0; k < 4; k++) acc[i][j][k] = 0.0f;

    auto load_tiles = [&](int stage, int kt) {
        uint32_t* As2 = smem + stage * STAGE_U32;
        uint32_t* Bs2 = As2 + AS_BUF;
        int kp0 = kt * 16;
#pragma unroll
        for (int t = 0; t < 2; t++) {
            int idx = t * 256 + tid;
            int r = idx >> 2;
            int kc = (idx & 3) << 2;
            cp_async16(&As2[r * AS_STRIDE + kc],
                       A + (m0 + r) * 128 + kp0 + kc);
        }
#pragma unroll
        for (int t = 0; t < 2; t++) {
            int idx = t * 256 + tid;
            int r = idx >> 5;
            int nc = (idx & 31) << 2;
            cp_async16(&Bs2[r * BS_STRIDE + nc],
                       B + (kp0 + r) * 256 + n0 + nc);
        }
        cp_commit();
    };

    load_tiles(0, 0);
    load_tiles(1, 1);

#pragma unroll 4
    for (int kt = 0; kt < 8; kt++) {
        int stage = kt % 3;
        // own group for kt done when <=1 newer pending (kt+1); last iter: drain all
        if (kt < 7) { cp_wait<1>(); } else { cp_wait<0>(); }
        __syncthreads();    // all warps: data visible AND finished mma(kt-1)
        if (kt + 2 < 8) load_tiles((kt + 2) % 3, kt + 2);

        const uint32_t* as = smem + stage * STAGE_U32;
        const uint32_t* bs = as + AS_BUF;
#pragma unroll
        for (int ks = 0; ks < 2; ks++) {
            int kk2 = ks * 8;
            uint32_t afr[4][4];
#pragma unroll
            for (int mi = 0; mi < 4; mi++) {
                int rb = wm + mi * 16 + lds_row_off;
                ldsm_x4(afr[mi][0], afr[mi][1], afr[mi][2], afr[mi][3],
                        &as[rb * AS_STRIDE + kk2 + lds_col_off]);
            }
            uint32_t bfr[4][2];
#pragma unroll
            for (int ni = 0; ni < 4; ni++) {
                int nb = wn + ni * 8 + grp;
                bfr[ni][0] = bs[(kk2 + tig) * BS_STRIDE + nb];
                bfr[ni][1] = bs[(kk2 + tig + 4) * BS_STRIDE + nb];
            }
#pragma unroll
            for (int mi = 0; mi < 4; mi++)
#pragma unroll
                for (int ni = 0; ni < 4; ni++)
                    mma_f16(acc[mi][ni],
                            afr[mi][0], afr[mi][1], afr[mi][2], afr[mi][3],
                            bfr[ni][0], bfr[ni][1]);
        }
    }

    // epilogue: scale by (1+ew[p]) and add mask[b,p]*eb[b] (fp16 mask value)
    const __half2* maskb = g_maskh + b * 128;
    float ebb = eb[b];
#pragma unroll
    for (int mi = 0; mi < 4; mi++) {
#pragma unroll
        for (int h = 0; h < 2; h++) {
            int p = m0 + wm + mi * 16 + grp + h * 8;
            float scale = 1.0f + ew[p];
            __half2 mh = maskb[p >> 1];
            float mval = (p & 1) ? __high2float(mh) : __low2float(mh);
            float addv = mval * ebb;
            long rowoff = ((long)(b * 256 + p)) * 256;
#pragma unroll
            for (int ni = 0; ni < 4; ni++) {
                int d = n0 + wn + ni * 8 + tig * 2;
                float v0 = acc[mi][ni][h * 2 + 0] * scale + addv;
                float v1 = acc[mi][ni][h * 2 + 1] * scale + addv;
                *(float2*)(out + rowoff + d) = make_float2(v0, v1);
            }
        }
    }
}

// ---------------- launch -----------------------------------------------------
extern "C" void kernel_launch(void* const* d_in, const int* in_sizes, int n_in,
                              void* d_out, int out_size) {
    const float* x    = (const float*)d_in[0];
    const float* prev = (const float*)d_in[1];
    const float* few  = (const float*)d_in[2];
    const float* feb  = (const float*)d_in[3];
    const float* lnew = (const float*)d_in[4];
    const float* lneb = (const float*)d_in[5];
    const float* lncw = (const float*)d_in[6];
    const float* lncb = (const float*)d_in[7];
    const float* lnpw = (const float*)d_in[8];
    const float* lnpb = (const float*)d_in[9];
    const float* diw  = (const float*)d_in[10];
    const float* dib  = (const float*)d_in[11];
    const float* embc = (const float*)d_in[12];
    const float* embp = (const float*)d_in[13];
    const float* ew   = (const float*)d_in[14];
    const float* ebia = (const float*)d_in[15];
    float* out = (float*)d_out;

    static bool attr_set = false;
    if (!attr_set) {
        cudaFuncSetAttribute(out_gemm_kernel,
                             cudaFuncAttributeMaxDynamicSharedMemorySize,
                             GEMM_SMEM_BYTES);
        attr_set = true;
    }

    xemb_prep_kernel<<<4608, 256>>>(x, few, feb, lnew, lneb,
                                    embp, lnpw, lnpb, prev, embc, lncw, lncb);
    xprompt_kernel<<<dim3(8, 8), dim3(16, 16)>>>(diw, dib, embp);
    logits_kernel<<<dim3(8, 8), dim3(16, 16)>>>();
    softmax_kernel<<<256, 32>>>();
    out_gemm_kernel<<<dim3(2, 2, 256), 256, GEMM_SMEM_BYTES>>>(ew, ebia, out);
}

// round 10
// speedup vs baseline: 2.1497x; 1.0040x over previous
#include <cuda_runtime.h>
#include <cuda_fp16.h>
#include <cstdint>

// Problem constants: B=C=P=D=256
#define N256 256
#define EPS 1e-5f

// ---------------- scratch (device globals; no allocations allowed) ----------
__device__ __half2 g_xembh[256 * 128 * 256]; // [b][c/2][d] k-pair-packed halves
__device__ __half2 g_maskh[256 * 128];       // [p][c/2] k-pair-packed halves
__device__ float g_xprompt[256 * 256];       // [P,D]
__device__ float g_xcol[256 * 256];          // [C,D] LN(emb_column)
__device__ float g_xpin[256 * 512];          // [P,2D]
__device__ float g_logits[256 * 256];        // [P,C]

// ---------------- helpers ----------------------------------------------------
__device__ __forceinline__ void cp_async16(void* smem, const void* gmem) {
    uint32_t s = (uint32_t)__cvta_generic_to_shared(smem);
    asm volatile("cp.async.cg.shared.global [%0], [%1], 16;" :: "r"(s), "l"(gmem));
}
__device__ __forceinline__ void cp_commit() {
    asm volatile("cp.async.commit_group;" ::: "memory");
}
template <int N>
__device__ __forceinline__ void cp_wait() {
    asm volatile("cp.async.wait_group %0;" :: "n"(N) : "memory");
}
__device__ __forceinline__ void ldsm_x4(uint32_t& r0, uint32_t& r1,
                                        uint32_t& r2, uint32_t& r3,
                                        const void* smem_ptr) {
    uint32_t a = (uint32_t)__cvta_generic_to_shared(smem_ptr);
    asm volatile("ldmatrix.sync.aligned.m8n8.x4.shared.b16 {%0,%1,%2,%3}, [%4];"
                 : "=r"(r0), "=r"(r1), "=r"(r2), "=r"(r3) : "r"(a));
}

// dual warp+block reduce
__device__ __forceinline__ void block_sum2_256(float& a, float& b,
                                               float* s8a, float* s8b) {
    int lane = threadIdx.x & 31, wid = threadIdx.x >> 5;
#pragma unroll
    for (int off = 16; off > 0; off >>= 1) {
        a += __shfl_xor_sync(0xffffffff, a, off);
        b += __shfl_xor_sync(0xffffffff, b, off);
    }
    if (lane == 0) { s8a[wid] = a; s8b[wid] = b; }
    __syncthreads();
    a = s8a[0]; b = s8b[0];
#pragma unroll
    for (int i = 1; i < 8; i++) { a += s8a[i]; b += s8b[i]; }
}

// ---------------- K1a: xemb pairs (grid 4096) --------------------------------
__global__ void xemb_kernel(const float* __restrict__ x,
                            const float* __restrict__ few,
                            const float* __restrict__ feb,
                            const float* __restrict__ lnew,
                            const float* __restrict__ lneb) {
    __shared__ float sbuf[6 * 256];
    int tid = threadIdx.x;
    float* sw0 = sbuf;
    float* sb0 = sbuf + 256;
    float* sw1 = sbuf + 512;
    float* sb1 = sbuf + 768;
    float* slw = sbuf + 1024;
    float* slb = sbuf + 1280;
    int c2 = blockIdx.x >> 5;
    int bg = blockIdx.x & 31;
    int c0 = c2 * 2, c1 = c0 + 1;
    sw0[tid] = few[c0 * 256 + tid];
    sb0[tid] = feb[c0 * 256 + tid];
    sw1[tid] = few[c1 * 256 + tid];
    sb1[tid] = feb[c1 * 256 + tid];
    slw[tid] = lnew[tid];
    slb[tid] = lneb[tid];
    __syncthreads();

    int lane = tid & 31;
    int wid = tid >> 5;
    int b = bg * 8 + wid;
    float xv0 = x[b * 256 + c0];
    float xv1 = x[b * 256 + c1];
    float v0[8], v1[8];
    float s0 = 0.f, q0 = 0.f, s1 = 0.f, q1 = 0.f;
#pragma unroll
    for (int i = 0; i < 8; i++) {
        int d = lane + i * 32;
        float t0 = fmaf(xv0, sw0[d], sb0[d]);
        float t1 = fmaf(xv1, sw1[d], sb1[d]);
        t0 = t0 > 0.f ? t0 : 0.f;
        t1 = t1 > 0.f ? t1 : 0.f;
        v0[i] = t0; v1[i] = t1;
        s0 += t0; q0 = fmaf(t0, t0, q0);
        s1 += t1; q1 = fmaf(t1, t1, q1);
    }
#pragma unroll
    for (int off = 16; off > 0; off >>= 1) {
        s0 += __shfl_xor_sync(0xffffffff, s0, off);
        q0 += __shfl_xor_sync(0xffffffff, q0, off);
        s1 += __shfl_xor_sync(0xffffffff, s1, off);
        q1 += __shfl_xor_sync(0xffffffff, q1, off);
    }
    float mu0 = s0 * (1.f / 256.f);
    float rs0 = rsqrtf(q0 * (1.f / 256.f) - mu0 * mu0 + EPS);
    float mu1 = s1 * (1.f / 256.f);
    float rs1 = rsqrtf(q1 * (1.f / 256.f) - mu1 * mu1 + EPS);
    __half2* orow = g_xembh + ((long)b * 128 + c2) * 256;
#pragma unroll
    for (int i = 0; i < 8; i++) {
        int d = lane + i * 32;
        float o0 = (v0[i] - mu0) * rs0 * slw[d] + slb[d];
        float o1 = (v1[i] - mu1) * rs1 * slw[d] + slb[d];
        orow[d] = __floats2half2_rn(o0, o1);
    }
}

// ---------------- K1b: prep (grid 512) ---------------------------------------
__global__ void prep_kernel(const float* __restrict__ embp,
                            const float* __restrict__ lnpw,
                            const float* __restrict__ lnpb,
                            const float* __restrict__ prev,
                            const float* __restrict__ embc,
                            const float* __restrict__ lncw,
                            const float* __restrict__ lncb) {
    __shared__ float s8a[8], s8b[8];
    int d = threadIdx.x;
    if (blockIdx.x < 256) {
        int p = blockIdx.x;
        float v = embp[p * N256 + d];
        float a = v, bq = v * v;
        block_sum2_256(a, bq, s8a, s8b);
        float mu = a * (1.f / 256.f);
        float rstd = rsqrtf(bq * (1.f / 256.f) - mu * mu + EPS);
        g_xpin[p * 512 + d] = (v - mu) * rstd * lnpw[d] + lnpb[d];
        g_xpin[p * 512 + 256 + d] = prev[p * N256 + d];
    } else {
        int c = blockIdx.x - 256;
        float v = embc[c * N256 + d];
        float a = v, bq = v * v;
        block_sum2_256(a, bq, s8a, s8b);
        float mu = a * (1.f / 256.f);
        float rstd = rsqrtf(bq * (1.f / 256.f) - mu * mu + EPS);
        g_xcol[c * N256 + d] = (v - mu) * rstd * lncw[d] + lncb[d];
    }
}

// ---------------- K2: x_prompt = xp_in @ W^T + b + emb_prompt ---------------
__global__ void xprompt_kernel(const float* __restrict__ W,
                               const float* __restrict__ bias,
                               const float* __restrict__ embp) {
    __shared__ float As[32][17];
    __shared__ float Ws[32][17];
    int tx = threadIdx.x, ty = threadIdx.y;
    int t = ty * 16 + tx;
    int p0 = blockIdx.y * 32;
    int d0 = blockIdx.x * 32;
    float acc[2][2] = {{0.f, 0.f}, {0.f, 0.f}};
    for (int kt = 0; kt < 32; kt++) {
        int k0 = kt * 16;
#pragma unroll
        for (int i = 0; i < 2; i++) {
            int idx = i * 256 + t;
            int r = idx >> 4, k = idx & 15;
            As[r][k] = g_xpin[(p0 + r) * 512 + k0 + k];
            Ws[r][k] = W[(d0 + r) * 512 + k0 + k];
        }
        __syncthreads();
#pragma unroll
        for (int kk = 0; kk < 16; kk++) {
            float a0 = As[ty * 2][kk], a1 = As[ty * 2 + 1][kk];
            float b0 = Ws[tx * 2][kk], b1 = Ws[tx * 2 + 1][kk];
            acc[0][0] += a0 * b0; acc[0][1] += a0 * b1;
            acc[1][0] += a1 * b0; acc[1][1] += a1 * b1;
        }
        __syncthreads();
    }
#pragma unroll
    for (int i = 0; i < 2; i++)
#pragma unroll
        for (int j = 0; j < 2; j++) {
            int p = p0 + ty * 2 + i, dd = d0 + tx * 2 + j;
            g_xprompt[p * N256 + dd] = acc[i][j] + bias[dd] + embp[p * N256 + dd];
        }
}

// ---------------- K3: logits = x_prompt @ x_col^T ---------------------------
__global__ void logits_kernel() {
    __shared__ float As[32][17];
    __shared__ float Bs[32][17];
    int tx = threadIdx.x, ty = threadIdx.y;
    int t = ty * 16 + tx;
    int p0 = blockIdx.y * 32;
    int c0 = blockIdx.x * 32;
    float acc[2][2] = {{0.f, 0.f}, {0.f, 0.f}};
    for (int kt = 0; kt < 16; kt++) {
        int k0 = kt * 16;
#pragma unroll
        for (int i = 0; i < 2; i++) {
            int idx = i * 256 + t;
            int r = idx >> 4, k = idx & 15;
            As[r][k] = g_xprompt[(p0 + r) * N256 + k0 + k];
            Bs[r][k] = g_xcol[(c0 + r) * N256 + k0 + k];
        }
        __syncthreads();
#pragma unroll
        for (int kk = 0; kk < 16; kk++) {
            float a0 = As[ty * 2][kk], a1 = As[ty * 2 + 1][kk];
            float b0 = Bs[tx * 2][kk], b1 = Bs[tx * 2 + 1][kk];
            acc[0][0] += a0 * b0; acc[0][1] += a0 * b1;
            acc[1][0] += a1 * b0; acc[1][1] += a1 * b1;
        }
        __syncthreads();
    }
#pragma unroll
    for (int i = 0; i < 2; i++)
#pragma unroll
        for (int j = 0; j < 2; j++)
            g_logits[(p0 + ty * 2 + i) * N256 + c0 + tx * 2 + j] = acc[i][j];
}

// ---------------- K4: warp-per-row softmax -----------------------------------
__global__ void softmax_kernel() {
    int lane = threadIdx.x;
    int p = blockIdx.x;
    const float* row = g_logits + p * N256;
    float4 v0 = __ldg((const float4*)(row + lane * 4));
    float4 v1 = __ldg((const float4*)(row + 128 + lane * 4));
    float m = fmaxf(fmaxf(fmaxf(v0.x, v0.y), fmaxf(v0.z, v0.w)),
                    fmaxf(fmaxf(v1.x, v1.y), fmaxf(v1.z, v1.w)));
#pragma unroll
    for (int off = 16; off > 0; off >>= 1)
        m = fmaxf(m, __shfl_xor_sync(0xffffffff, m, off));
    float e0 = expf(v0.x - m), e1 = expf(v0.y - m);
    float e2 = expf(v0.z - m), e3 = expf(v0.w - m);
    float f0 = expf(v1.x - m), f1 = expf(v1.y - m);
    float f2 = expf(v1.z - m), f3 = expf(v1.w - m);
    float s = e0 + e1 + e2 + e3 + f0 + f1 + f2 + f3;
#pragma unroll
    for (int off = 16; off > 0; off >>= 1)
        s += __shfl_xor_sync(0xffffffff, s, off);
    float inv = 1.0f / s;
    __half2* mrow = g_maskh + p * 128;
    mrow[lane * 2 + 0] = __floats2half2_rn(e0 * inv, e1 * inv);
    mrow[lane * 2 + 1] = __floats2half2_rn(e2 * inv, e3 * inv);
    mrow[64 + lane * 2 + 0] = __floats2half2_rn(f0 * inv, f1 * inv);
    mrow[64 + lane * 2 + 1] = __floats2half2_rn(f2 * inv, f3 * inv);
}

// ---------------- K5: out[b] = mask @ xemb[b], fp16 mma, 3-stage pipeline ---
__device__ __forceinline__ void mma_f16(float c[4],
                                        uint32_t a0, uint32_t a1, uint32_t a2, uint32_t a3,
                                        uint32_t b0, uint32_t b1) {
    asm volatile(
        "mma.sync.aligned.m16n8k16.row.col.f32.f16.f16.f32 "
        "{%0,%1,%2,%3}, {%4,%5,%6,%7}, {%8,%9}, {%0,%1,%2,%3};"
        : "+f"(c[0]), "+f"(c[1]), "+f"(c[2]), "+f"(c[3])
        : "r"(a0), "r"(a1), "r"(a2), "r"(a3), "r"(b0), "r"(b1));
}

#define AS_STRIDE 20    // uint32: 16 + 4 pad
#define BS_STRIDE 136   // uint32: 128 + 8 pad
#define AS_BUF (128 * AS_STRIDE)
#define BS_BUF (16 * BS_STRIDE)
#define STAGE_U32 (AS_BUF + BS_BUF)
#define GEMM_SMEM_BYTES (3 * STAGE_U32 * 4)   // 56832 B

__global__ __launch_bounds__(256, 2) void out_gemm_kernel(
    const float* __restrict__ ew,
    const float* __restrict__ eb,
    float* __restrict__ out) {
    extern __shared__ __align__(16) uint32_t smem[];

    int b = blockIdx.z;
    int m0 = blockIdx.y * 128;
    int n0 = blockIdx.x * 128;
    const uint32_t* A = (const uint32_t*)g_maskh;                     // [256][128]
    const uint32_t* B = (const uint32_t*)(g_xembh + (long)b * 32768); // [128][256]

    int tid = threadIdx.x;
    int lane = tid & 31;
    int warp = tid >> 5;
    int wm = (warp & 1) * 64;
    int wn = (warp >> 1) * 32;
    int grp = lane >> 2;
    int tig = lane & 3;

    int lrow = lane & 7;
    int lm = lane >> 3;
    int lds_row_off = lrow + ((lm & 1) << 3);
    int lds_col_off = (lm >> 1) << 2;

    float acc[4][4][4];
#pragma unroll
    for (int i = 0; i < 4; i++)
#pragma unroll
        for (int j = 0; j < 4; j++)
#pragma unroll
            for (int k = 0; k < 4; k++) acc[i][j][k] = 0.0f;

    auto load_tiles = [&](int stage, int kt) {
        uint32_t* As2 = smem + stage * STAGE_U32;
        uint32_t* Bs2 = As2 + AS_BUF;
        int kp0 = kt * 16;
#pragma unroll
        for (int t = 0; t < 2; t++) {
            int idx = t * 256 + tid;
            int r = idx >> 2;
            int kc = (idx & 3) << 2;
            cp_async16(&As2[r * AS_STRIDE + kc],
                       A + (m0 + r) * 128 + kp0 + kc);
        }
#pragma unroll
        for (int t = 0; t < 2; t++) {
            int idx = t * 256 + tid;
            int r = idx >> 5;
            int nc = (idx & 31) << 2;
            cp_async16(&Bs2[r * BS_STRIDE + nc],
                       B + (kp0 + r) * 256 + n0 + nc);
        }
        cp_commit();
    };

    load_tiles(0, 0);
    load_tiles(1, 1);

#pragma unroll 4
    for (int kt = 0; kt < 8; kt++) {
        int stage = kt % 3;
        if (kt < 7) { cp_wait<1>(); } else { cp_wait<0>(); }
        __syncthreads();
        if (kt + 2 < 8) load_tiles((kt + 2) % 3, kt + 2);

        const uint32_t* as = smem + stage * STAGE_U32;
        const uint32_t* bs = as + AS_BUF;
#pragma unroll
        for (int ks = 0; ks < 2; ks++) {
            int kk2 = ks * 8;
            uint32_t afr[4][4];
#pragma unroll
            for (int mi = 0; mi < 4; mi++) {
                int rb = wm + mi * 16 + lds_row_off;
                ldsm_x4(afr[mi][0], afr[mi][1], afr[mi][2], afr[mi][3],
                        &as[rb * AS_STRIDE + kk2 + lds_col_off]);
            }
            uint32_t bfr[4][2];
#pragma unroll
            for (int ni = 0; ni < 4; ni++) {
                int nb = wn + ni * 8 + grp;
                bfr[ni][0] = bs[(kk2 + tig) * BS_STRIDE + nb];
                bfr[ni][1] = bs[(kk2 + tig + 4) * BS_STRIDE + nb];
            }
#pragma unroll
            for (int mi = 0; mi < 4; mi++)
#pragma unroll
                for (int ni = 0; ni < 4; ni++)
                    mma_f16(acc[mi][ni],
                            afr[mi][0], afr[mi][1], afr[mi][2], afr[mi][3],
                            bfr[ni][0], bfr[ni][1]);
        }
    }

    // epilogue
    const __half2* maskb = g_maskh + b * 128;
    float ebb = eb[b];
#pragma unroll
    for (int mi = 0; mi < 4; mi++) {
#pragma unroll
        for (int h = 0; h < 2; h++) {
            int p = m0 + wm + mi * 16 + grp + h * 8;
            float scale = 1.0f + ew[p];
            __half2 mh = maskb[p >> 1];
            float mval = (p & 1) ? __high2float(mh) : __low2float(mh);
            float addv = mval * ebb;
            long rowoff = ((long)(b * 256 + p)) * 256;
#pragma unroll
            for (int ni = 0; ni < 4; ni++) {
                int d = n0 + wn + ni * 8 + tig * 2;
                float v0 = acc[mi][ni][h * 2 + 0] * scale + addv;
                float v1 = acc[mi][ni][h * 2 + 1] * scale + addv;
                *(float2*)(out + rowoff + d) = make_float2(v0, v1);
            }
        }
    }
}

// ---------------- launch -----------------------------------------------------
extern "C" void kernel_launch(void* const* d_in, const int* in_sizes, int n_in,
                              void* d_out, int out_size) {
    const float* x    = (const float*)d_in[0];
    const float* prev = (const float*)d_in[1];
    const float* few  = (const float*)d_in[2];
    const float* feb  = (const float*)d_in[3];
    const float* lnew = (const float*)d_in[4];
    const float* lneb = (const float*)d_in[5];
    const float* lncw = (const float*)d_in[6];
    const float* lncb = (const float*)d_in[7];
    const float* lnpw = (const float*)d_in[8];
    const float* lnpb = (const float*)d_in[9];
    const float* diw  = (const float*)d_in[10];
    const float* dib  = (const float*)d_in[11];
    const float* embc = (const float*)d_in[12];
    const float* embp = (const float*)d_in[13];
    const float* ew   = (const float*)d_in[14];
    const float* ebia = (const float*)d_in[15];
    float* out = (float*)d_out;

    static cudaStream_t s_chain;
    static cudaEvent_t ev_fork, ev_join;
    static bool init_done = false;
    if (!init_done) {
        cudaFuncSetAttribute(out_gemm_kernel,
                             cudaFuncAttributeMaxDynamicSharedMemorySize,
                             GEMM_SMEM_BYTES);
        cudaStreamCreateWithFlags(&s_chain, cudaStreamNonBlocking);
        cudaEventCreateWithFlags(&ev_fork, cudaEventDisableTiming);
        cudaEventCreateWithFlags(&ev_join, cudaEventDisableTiming);
        init_done = true;
    }

    // fork: chain kernels on s_chain, xemb on origin stream
    cudaEventRecord(ev_fork, 0);
    cudaStreamWaitEvent(s_chain, ev_fork, 0);

    prep_kernel<<<512, 256, 0, s_chain>>>(embp, lnpw, lnpb, prev,
                                          embc, lncw, lncb);
    xprompt_kernel<<<dim3(8, 8), dim3(16, 16), 0, s_chain>>>(diw, dib, embp);
    logits_kernel<<<dim3(8, 8), dim3(16, 16), 0, s_chain>>>();
    softmax_kernel<<<256, 32, 0, s_chain>>>();
    cudaEventRecord(ev_join, s_chain);

    xemb_kernel<<<4096, 256>>>(x, few, feb, lnew, lneb);

    // join: out_gemm needs both branches
    cudaStreamWaitEvent(0, ev_join, 0);
    out_gemm_kernel<<<dim3(2, 2, 256), 256, GEMM_SMEM_BYTES>>>(ew, ebia, out);
}

// round 11
// speedup vs baseline: 2.1607x; 1.0051x over previous
#include <cuda_runtime.h>
#include <cuda_fp16.h>
#include <cstdint>

// Problem constants: B=C=P=D=256
#define N256 256
#define EPS 1e-5f

// ---------------- scratch (device globals; no allocations allowed) ----------
__device__ __half2 g_xembh[256 * 128 * 256]; // [b][c/2][d] k-pair-packed halves
__device__ __half2 g_maskh[256 * 128];       // [p][c/2] k-pair-packed halves
__device__ float g_xprompt[256 * 256];       // [P,D]
__device__ float g_logits[256 * 256];        // [P,C]
__device__ int g_cnt[8];                     // arrival counters (zero-init, self-resetting)

// ---------------- helpers ----------------------------------------------------
__device__ __forceinline__ void cp_async16(void* smem, const void* gmem) {
    uint32_t s = (uint32_t)__cvta_generic_to_shared(smem);
    asm volatile("cp.async.cg.shared.global [%0], [%1], 16;" :: "r"(s), "l"(gmem));
}
__device__ __forceinline__ void cp_commit() {
    asm volatile("cp.async.commit_group;" ::: "memory");
}
template <int N>
__device__ __forceinline__ void cp_wait() {
    asm volatile("cp.async.wait_group %0;" :: "n"(N) : "memory");
}
__device__ __forceinline__ void ldsm_x4(uint32_t& r0, uint32_t& r1,
                                        uint32_t& r2, uint32_t& r3,
                                        const void* smem_ptr) {
    uint32_t a = (uint32_t)__cvta_generic_to_shared(smem_ptr);
    asm volatile("ldmatrix.sync.aligned.m8n8.x4.shared.b16 {%0,%1,%2,%3}, [%4];"
                 : "=r"(r0), "=r"(r1), "=r"(r2), "=r"(r3) : "r"(a));
}

// per-32-row LN stats: 8 threads per row, each reads 8 float4s.
// writes smu[32], srs[32]. 256-thread block, rows at src + (row0+r)*256.
__device__ __forceinline__ void row_stats_32(const float* __restrict__ src,
                                             int row0, float* smu, float* srs) {
    int t = threadIdx.y * blockDim.x + threadIdx.x;
    int r = t >> 3, j = t & 7;
    const float4* base4 = (const float4*)(src + (row0 + r) * 256);
    float s = 0.f, q = 0.f;
#pragma unroll
    for (int i = 0; i < 8; i++) {
        float4 v = base4[j + i * 8];
        s += v.x + v.y + v.z + v.w;
        q = fmaf(v.x, v.x, q); q = fmaf(v.y, v.y, q);
        q = fmaf(v.z, v.z, q); q = fmaf(v.w, v.w, q);
    }
#pragma unroll
    for (int off = 4; off > 0; off >>= 1) {
        s += __shfl_xor_sync(0xffffffffu, s, off, 8);
        q += __shfl_xor_sync(0xffffffffu, q, off, 8);
    }
    if (j == 0) {
        float mu = s * (1.f / 256.f);
        smu[r] = mu;
        srs[r] = rsqrtf(q * (1.f / 256.f) - mu * mu + EPS);
    }
}

// ---------------- K1: xemb pairs (grid 4096) ---------------------------------
__global__ void xemb_kernel(const float* __restrict__ x,
                            const float* __restrict__ few,
                            const float* __restrict__ feb,
                            const float* __restrict__ lnew,
                            const float* __restrict__ lneb) {
    __shared__ float sbuf[6 * 256];
    int tid = threadIdx.x;
    float* sw0 = sbuf;
    float* sb0 = sbuf + 256;
    float* sw1 = sbuf + 512;
    float* sb1 = sbuf + 768;
    float* slw = sbuf + 1024;
    float* slb = sbuf + 1280;
    int c2 = blockIdx.x >> 5;
    int bg = blockIdx.x & 31;
    int c0 = c2 * 2, c1 = c0 + 1;
    sw0[tid] = few[c0 * 256 + tid];
    sb0[tid] = feb[c0 * 256 + tid];
    sw1[tid] = few[c1 * 256 + tid];
    sb1[tid] = feb[c1 * 256 + tid];
    slw[tid] = lnew[tid];
    slb[tid] = lneb[tid];
    __syncthreads();

    int lane = tid & 31;
    int wid = tid >> 5;
    int b = bg * 8 + wid;
    float xv0 = x[b * 256 + c0];
    float xv1 = x[b * 256 + c1];
    float v0[8], v1[8];
    float s0 = 0.f, q0 = 0.f, s1 = 0.f, q1 = 0.f;
#pragma unroll
    for (int i = 0; i < 8; i++) {
        int d = lane + i * 32;
        float t0 = fmaf(xv0, sw0[d], sb0[d]);
        float t1 = fmaf(xv1, sw1[d], sb1[d]);
        t0 = t0 > 0.f ? t0 : 0.f;
        t1 = t1 > 0.f ? t1 : 0.f;
        v0[i] = t0; v1[i] = t1;
        s0 += t0; q0 = fmaf(t0, t0, q0);
        s1 += t1; q1 = fmaf(t1, t1, q1);
    }
#pragma unroll
    for (int off = 16; off > 0; off >>= 1) {
        s0 += __shfl_xor_sync(0xffffffff, s0, off);
        q0 += __shfl_xor_sync(0xffffffff, q0, off);
        s1 += __shfl_xor_sync(0xffffffff, s1, off);
        q1 += __shfl_xor_sync(0xffffffff, q1, off);
    }
    float mu0 = s0 * (1.f / 256.f);
    float rs0 = rsqrtf(q0 * (1.f / 256.f) - mu0 * mu0 + EPS);
    float mu1 = s1 * (1.f / 256.f);
    float rs1 = rsqrtf(q1 * (1.f / 256.f) - mu1 * mu1 + EPS);
    __half2* orow = g_xembh + ((long)b * 128 + c2) * 256;
#pragma unroll
    for (int i = 0; i < 8; i++) {
        int d = lane + i * 32;
        float o0 = (v0[i] - mu0) * rs0 * slw[d] + slb[d];
        float o1 = (v1[i] - mu1) * rs1 * slw[d] + slb[d];
        orow[d] = __floats2half2_rn(o0, o1);
    }
}

// ---------------- K2: x_prompt = [LN(embp)|prev] @ W^T + b + embp -----------
// LN computed on the fly (prep fused). 32x32 tiles, 2x2/thread, K=512.
__global__ void xprompt_fused(const float* __restrict__ W,
                              const float* __restrict__ bias,
                              const float* __restrict__ embp,
                              const float* __restrict__ lnpw,
                              const float* __restrict__ lnpb,
                              const float* __restrict__ prev) {
    __shared__ float As[32][17];
    __shared__ float Ws[32][17];
    __shared__ float smu[32], srs[32];
    int tx = threadIdx.x, ty = threadIdx.y;
    int t = ty * 16 + tx;
    int p0 = blockIdx.y * 32;
    int d0 = blockIdx.x * 32;

    row_stats_32(embp, p0, smu, srs);
    __syncthreads();

    float acc[2][2] = {{0.f, 0.f}, {0.f, 0.f}};
    for (int kt = 0; kt < 32; kt++) {
        int k0 = kt * 16;
#pragma unroll
        for (int i = 0; i < 2; i++) {
            int idx = i * 256 + t;
            int r = idx >> 4, k = idx & 15;
            int gk = k0 + k;
            float v;
            if (gk < 256)
                v = (embp[(p0 + r) * 256 + gk] - smu[r]) * srs[r] * lnpw[gk] + lnpb[gk];
            else
                v = prev[(p0 + r) * 256 + gk - 256];
            As[r][k] = v;
            Ws[r][k] = W[(d0 + r) * 512 + gk];
        }
        __syncthreads();
#pragma unroll
        for (int kk = 0; kk < 16; kk++) {
            float a0 = As[ty * 2][kk], a1 = As[ty * 2 + 1][kk];
            float b0 = Ws[tx * 2][kk], b1 = Ws[tx * 2 + 1][kk];
            acc[0][0] += a0 * b0; acc[0][1] += a0 * b1;
            acc[1][0] += a1 * b0; acc[1][1] += a1 * b1;
        }
        __syncthreads();
    }
#pragma unroll
    for (int i = 0; i < 2; i++)
#pragma unroll
        for (int j = 0; j < 2; j++) {
            int p = p0 + ty * 2 + i, dd = d0 + tx * 2 + j;
            g_xprompt[p * N256 + dd] = acc[i][j] + bias[dd] + embp[p * N256 + dd];
        }
}

// ---------------- K3: logits = x_prompt @ LN(embc)^T, softmax fused ----------
// LN(emb_column) computed on the fly; the last block per 32-row group does the
// row softmax (threadfence + arrival counter; counter self-resets).
__global__ void logits_fused(const float* __restrict__ embc,
                             const float* __restrict__ lncw,
                             const float* __restrict__ lncb) {
    __shared__ float As[32][17];
    __shared__ float Bs[32][17];
    __shared__ float smu[32], srs[32];
    __shared__ int sflag;
    int tx = threadIdx.x, ty = threadIdx.y;
    int t = ty * 16 + tx;
    int p0 = blockIdx.y * 32;
    int c0 = blockIdx.x * 32;

    row_stats_32(embc, c0, smu, srs);
    __syncthreads();

    float acc[2][2] = {{0.f, 0.f}, {0.f, 0.f}};
    for (int kt = 0; kt < 16; kt++) {
        int k0 = kt * 16;
#pragma unroll
        for (int i = 0; i < 2; i++) {
            int idx = i * 256 + t;
            int r = idx >> 4, k = idx & 15;
            int gk = k0 + k;
            As[r][k] = g_xprompt[(p0 + r) * N256 + gk];
            Bs[r][k] = (embc[(c0 + r) * 256 + gk] - smu[r]) * srs[r] * lncw[gk] + lncb[gk];
        }
        __syncthreads();
#pragma unroll
        for (int kk = 0; kk < 16; kk++) {
            float a0 = As[ty * 2][kk], a1 = As[ty * 2 + 1][kk];
            float b0 = Bs[tx * 2][kk], b1 = Bs[tx * 2 + 1][kk];
            acc[0][0] += a0 * b0; acc[0][1] += a0 * b1;
            acc[1][0] += a1 * b0; acc[1][1] += a1 * b1;
        }
        __syncthreads();
    }
#pragma unroll
    for (int i = 0; i < 2; i++)
#pragma unroll
        for (int j = 0; j < 2; j++)
            g_logits[(p0 + ty * 2 + i) * N256 + c0 + tx * 2 + j] = acc[i][j];

    // arrival counting: 8 blocks per p-row group
    __threadfence();
    __syncthreads();
    if (t == 0) {
        int old = atomicAdd(&g_cnt[blockIdx.y], 1);
        sflag = (old == 7);
    }
    __syncthreads();
    if (!sflag) return;

    // last block: softmax for rows p0..p0+31 (8 warps x 4 rows each)
    int lane = t & 31;
    int warp = t >> 5;
#pragma unroll
    for (int q = 0; q < 4; q++) {
        int p = p0 + warp * 4 + q;
        const float* row = g_logits + p * N256;
        float4 v0 = *(const float4*)(row + lane * 4);
        float4 v1 = *(const float4*)(row + 128 + lane * 4);
        float m = fmaxf(fmaxf(fmaxf(v0.x, v0.y), fmaxf(v0.z, v0.w)),
                        fmaxf(fmaxf(v1.x, v1.y), fmaxf(v1.z, v1.w)));
#pragma unroll
        for (int off = 16; off > 0; off >>= 1)
            m = fmaxf(m, __shfl_xor_sync(0xffffffff, m, off));
        float e0 = expf(v0.x - m), e1 = expf(v0.y - m);
        float e2 = expf(v0.z - m), e3 = expf(v0.w - m);
        float f0 = expf(v1.x - m), f1 = expf(v1.y - m);
        float f2 = expf(v1.z - m), f3 = expf(v1.w - m);
        float s = e0 + e1 + e2 + e3 + f0 + f1 + f2 + f3;
#pragma unroll
        for (int off = 16; off > 0; off >>= 1)
            s += __shfl_xor_sync(0xffffffff, s, off);
        float inv = 1.0f / s;
        __half2* mrow = g_maskh + p * 128;
        mrow[lane * 2 + 0] = __floats2half2_rn(e0 * inv, e1 * inv);
        mrow[lane * 2 + 1] = __floats2half2_rn(e2 * inv, e3 * inv);
        mrow[64 + lane * 2 + 0] = __floats2half2_rn(f0 * inv, f1 * inv);
        mrow[64 + lane * 2 + 1] = __floats2half2_rn(f2 * inv, f3 * inv);
    }
    if (t == 0) g_cnt[blockIdx.y] = 0;   // reset for next graph replay
}

// ---------------- K4: out[b] = mask @ xemb[b], fp16 mma, 3-stage pipeline ---
__device__ __forceinline__ void mma_f16(float c[4],
                                        uint32_t a0, uint32_t a1, uint32_t a2, uint32_t a3,
                                        uint32_t b0, uint32_t b1) {
    asm volatile(
        "mma.sync.aligned.m16n8k16.row.col.f32.f16.f16.f32 "
        "{%0,%1,%2,%3}, {%4,%5,%6,%7}, {%8,%9}, {%0,%1,%2,%3};"
        : "+f"(c[0]), "+f"(c[1]), "+f"(c[2]), "+f"(c[3])
        : "r"(a0), "r"(a1), "r"(a2), "r"(a3), "r"(b0), "r"(b1));
}

#define AS_STRIDE 20    // uint32: 16 + 4 pad
#define BS_STRIDE 136   // uint32: 128 + 8 pad
#define AS_BUF (128 * AS_STRIDE)
#define BS_BUF (16 * BS_STRIDE)
#define STAGE_U32 (AS_BUF + BS_BUF)
#define GEMM_SMEM_BYTES (3 * STAGE_U32 * 4)   // 56832 B

__global__ __launch_bounds__(256, 2) void out_gemm_kernel(
    const float* __restrict__ ew,
    const float* __restrict__ eb,
    float* __restrict__ out) {
    extern __shared__ __align__(16) uint32_t smem[];

    int b = blockIdx.z;
    int m0 = blockIdx.y * 128;
    int n0 = blockIdx.x * 128;
    const uint32_t* A = (const uint32_t*)g_maskh;                     // [256][128]
    const uint32_t* B = (const uint32_t*)(g_xembh + (long)b * 32768); // [128][256]

    int tid = threadIdx.x;
    int lane = tid & 31;
    int warp = tid >> 5;
    int wm = (warp & 1) * 64;
    int wn = (warp >> 1) * 32;
    int grp = lane >> 2;
    int tig = lane & 3;

    int lrow = lane & 7;
    int lm = lane >> 3;
    int lds_row_off = lrow + ((lm & 1) << 3);
    int lds_col_off = (lm >> 1) << 2;

    float acc[4][4][4];
#pragma unroll
    for (int i = 0; i < 4; i++)
#pragma unroll
        for (int j = 0; j < 4; j++)
#pragma unroll
            for (int k = 0; k < 4; k++) acc[i][j][k] = 0.0f;

    auto load_tiles = [&](int stage, int kt) {
        uint32_t* As2 = smem + stage * STAGE_U32;
        uint32_t* Bs2 = As2 + AS_BUF;
        int kp0 = kt * 16;
#pragma unroll
        for (int t = 0; t < 2; t++) {
            int idx = t * 256 + tid;
            int r = idx >> 2;
            int kc = (idx & 3) << 2;
            cp_async16(&As2[r * AS_STRIDE + kc],
                       A + (m0 + r) * 128 + kp0 + kc);
        }
#pragma unroll
        for (int t = 0; t < 2; t++) {
            int idx = t * 256 + tid;
            int r = idx >> 5;
            int nc = (idx & 31) << 2;
            cp_async16(&Bs2[r * BS_STRIDE + nc],
                       B + (kp0 + r) * 256 + n0 + nc);
        }
        cp_commit();
    };

    load_tiles(0, 0);
    load_tiles(1, 1);

#pragma unroll 4
    for (int kt = 0; kt < 8; kt++) {
        int stage = kt % 3;
        if (kt < 7) { cp_wait<1>(); } else { cp_wait<0>(); }
        __syncthreads();
        if (kt + 2 < 8) load_tiles((kt + 2) % 3, kt + 2);

        const uint32_t* as = smem + stage * STAGE_U32;
        const uint32_t* bs = as + AS_BUF;
#pragma unroll
        for (int ks = 0; ks < 2; ks++) {
            int kk2 = ks * 8;
            uint32_t afr[4][4];
#pragma unroll
            for (int mi = 0; mi < 4; mi++) {
                int rb = wm + mi * 16 + lds_row_off;
                ldsm_x4(afr[mi][0], afr[mi][1], afr[mi][2], afr[mi][3],
                        &as[rb * AS_STRIDE + kk2 + lds_col_off]);
            }
            uint32_t bfr[4][2];
#pragma unroll
            for (int ni = 0; ni < 4; ni++) {
                int nb = wn + ni * 8 + grp;
                bfr[ni][0] = bs[(kk2 + tig) * BS_STRIDE + nb];
                bfr[ni][1] = bs[(kk2 + tig + 4) * BS_STRIDE + nb];
            }
#pragma unroll
            for (int mi = 0; mi < 4; mi++)
#pragma unroll
                for (int ni = 0; ni < 4; ni++)
                    mma_f16(acc[mi][ni],
                            afr[mi][0], afr[mi][1], afr[mi][2], afr[mi][3],
                            bfr[ni][0], bfr[ni][1]);
        }
    }

    // epilogue
    const __half2* maskb = g_maskh + b * 128;
    float ebb = eb[b];
#pragma unroll
    for (int mi = 0; mi < 4; mi++) {
#pragma unroll
        for (int h = 0; h < 2; h++) {
            int p = m0 + wm + mi * 16 + grp + h * 8;
            float scale = 1.0f + ew[p];
            __half2 mh = maskb[p >> 1];
            float mval = (p & 1) ? __high2float(mh) : __low2float(mh);
            float addv = mval * ebb;
            long rowoff = ((long)(b * 256 + p)) * 256;
#pragma unroll
            for (int ni = 0; ni < 4; ni++) {
                int d = n0 + wn + ni * 8 + tig * 2;
                float v0 = acc[mi][ni][h * 2 + 0] * scale + addv;
                float v1 = acc[mi][ni][h * 2 + 1] * scale + addv;
                *(float2*)(out + rowoff + d) = make_float2(v0, v1);
            }
        }
    }
}

// ---------------- launch -----------------------------------------------------
extern "C" void kernel_launch(void* const* d_in, const int* in_sizes, int n_in,
                              void* d_out, int out_size) {
    const float* x    = (const float*)d_in[0];
    const float* prev = (const float*)d_in[1];
    const float* few  = (const float*)d_in[2];
    const float* feb  = (const float*)d_in[3];
    const float* lnew = (const float*)d_in[4];
    const float* lneb = (const float*)d_in[5];
    const float* lncw = (const float*)d_in[6];
    const float* lncb = (const float*)d_in[7];
    const float* lnpw = (const float*)d_in[8];
    const float* lnpb = (const float*)d_in[9];
    const float* diw  = (const float*)d_in[10];
    const float* dib  = (const float*)d_in[11];
    const float* embc = (const float*)d_in[12];
    const float* embp = (const float*)d_in[13];
    const float* ew   = (const float*)d_in[14];
    const float* ebia = (const float*)d_in[15];
    float* out = (float*)d_out;

    static cudaStream_t s_chain;
    static cudaEvent_t ev_fork, ev_join;
    static bool init_done = false;
    if (!init_done) {
        cudaFuncSetAttribute(out_gemm_kernel,
                             cudaFuncAttributeMaxDynamicSharedMemorySize,
                             GEMM_SMEM_BYTES);
        cudaStreamCreateWithFlags(&s_chain, cudaStreamNonBlocking);
        cudaEventCreateWithFlags(&ev_fork, cudaEventDisableTiming);
        cudaEventCreateWithFlags(&ev_join, cudaEventDisableTiming);
        init_done = true;
    }

    // fork: chain on s_chain, xemb on origin stream
    cudaEventRecord(ev_fork, 0);
    cudaStreamWaitEvent(s_chain, ev_fork, 0);

    xprompt_fused<<<dim3(8, 8), dim3(16, 16), 0, s_chain>>>(diw, dib, embp,
                                                            lnpw, lnpb, prev);
    logits_fused<<<dim3(8, 8), dim3(16, 16), 0, s_chain>>>(embc, lncw, lncb);
    cudaEventRecord(ev_join, s_chain);

    xemb_kernel<<<4096, 256>>>(x, few, feb, lnew, lneb);

    // join: out_gemm needs both branches
    cudaStreamWaitEvent(0, ev_join, 0);
    out_gemm_kernel<<<dim3(2, 2, 256), 256, GEMM_SMEM_BYTES>>>(ew, ebia, out);
}

// round 12
// speedup vs baseline: 2.3350x; 1.0807x over previous
#include <cuda_runtime.h>
#include <cuda_fp16.h>
#include <cstdint>

// Problem constants: B=C=P=D=256
#define N256 256
#define EPS 1e-5f

// ---------------- scratch (device globals; no allocations allowed) ----------
__device__ __half2 g_xembh[256 * 128 * 256]; // [b][c/2][d] k-pair-packed halves
__device__ __half2 g_maskh[256 * 128];       // [p][c/2] k-pair-packed halves
__device__ float g_xprompt[256 * 256];       // [P,D]
__device__ float g_logits[256 * 256];        // [P,C]
__device__ int g_cnt[8];                     // arrival counters (zero-init, self-resetting)

// ---------------- helpers ----------------------------------------------------
__device__ __forceinline__ void cp_async16(void* smem, const void* gmem) {
    uint32_t s = (uint32_t)__cvta_generic_to_shared(smem);
    asm volatile("cp.async.cg.shared.global [%0], [%1], 16;" :: "r"(s), "l"(gmem));
}
__device__ __forceinline__ void cp_commit() {
    asm volatile("cp.async.commit_group;" ::: "memory");
}
template <int N>
__device__ __forceinline__ void cp_wait() {
    asm volatile("cp.async.wait_group %0;" :: "n"(N) : "memory");
}
__device__ __forceinline__ void ldsm_x4(uint32_t& r0, uint32_t& r1,
                                        uint32_t& r2, uint32_t& r3,
                                        const void* smem_ptr) {
    uint32_t a = (uint32_t)__cvta_generic_to_shared(smem_ptr);
    asm volatile("ldmatrix.sync.aligned.m8n8.x4.shared.b16 {%0,%1,%2,%3}, [%4];"
                 : "=r"(r0), "=r"(r1), "=r"(r2), "=r"(r3) : "r"(a));
}

// per-32-row LN stats: 8 threads per row, each reads 8 float4s.
__device__ __forceinline__ void row_stats_32(const float* __restrict__ src,
                                             int row0, float* smu, float* srs) {
    int t = threadIdx.y * blockDim.x + threadIdx.x;
    int r = t >> 3, j = t & 7;
    const float4* base4 = (const float4*)(src + (row0 + r) * 256);
    float s = 0.f, q = 0.f;
#pragma unroll
    for (int i = 0; i < 8; i++) {
        float4 v = base4[j + i * 8];
        s += v.x + v.y + v.z + v.w;
        q = fmaf(v.x, v.x, q); q = fmaf(v.y, v.y, q);
        q = fmaf(v.z, v.z, q); q = fmaf(v.w, v.w, q);
    }
#pragma unroll
    for (int off = 4; off > 0; off >>= 1) {
        s += __shfl_xor_sync(0xffffffffu, s, off, 8);
        q += __shfl_xor_sync(0xffffffffu, q, off, 8);
    }
    if (j == 0) {
        float mu = s * (1.f / 256.f);
        smu[r] = mu;
        srs[r] = rsqrtf(q * (1.f / 256.f) - mu * mu + EPS);
    }
}

// ---------------- K1: xemb pairs (grid 4096) ---------------------------------
__global__ void xemb_kernel(const float* __restrict__ x,
                            const float* __restrict__ few,
                            const float* __restrict__ feb,
                            const float* __restrict__ lnew,
                            const float* __restrict__ lneb) {
    __shared__ float sbuf[6 * 256];
    int tid = threadIdx.x;
    float* sw0 = sbuf;
    float* sb0 = sbuf + 256;
    float* sw1 = sbuf + 512;
    float* sb1 = sbuf + 768;
    float* slw = sbuf + 1024;
    float* slb = sbuf + 1280;
    int c2 = blockIdx.x >> 5;
    int bg = blockIdx.x & 31;
    int c0 = c2 * 2, c1 = c0 + 1;
    sw0[tid] = few[c0 * 256 + tid];
    sb0[tid] = feb[c0 * 256 + tid];
    sw1[tid] = few[c1 * 256 + tid];
    sb1[tid] = feb[c1 * 256 + tid];
    slw[tid] = lnew[tid];
    slb[tid] = lneb[tid];
    __syncthreads();

    int lane = tid & 31;
    int wid = tid >> 5;
    int b = bg * 8 + wid;
    float xv0 = x[b * 256 + c0];
    float xv1 = x[b * 256 + c1];
    float v0[8], v1[8];
    float s0 = 0.f, q0 = 0.f, s1 = 0.f, q1 = 0.f;
#pragma unroll
    for (int i = 0; i < 8; i++) {
        int d = lane + i * 32;
        float t0 = fmaf(xv0, sw0[d], sb0[d]);
        float t1 = fmaf(xv1, sw1[d], sb1[d]);
        t0 = t0 > 0.f ? t0 : 0.f;
        t1 = t1 > 0.f ? t1 : 0.f;
        v0[i] = t0; v1[i] = t1;
        s0 += t0; q0 = fmaf(t0, t0, q0);
        s1 += t1; q1 = fmaf(t1, t1, q1);
    }
#pragma unroll
    for (int off = 16; off > 0; off >>= 1) {
        s0 += __shfl_xor_sync(0xffffffff, s0, off);
        q0 += __shfl_xor_sync(0xffffffff, q0, off);
        s1 += __shfl_xor_sync(0xffffffff, s1, off);
        q1 += __shfl_xor_sync(0xffffffff, q1, off);
    }
    float mu0 = s0 * (1.f / 256.f);
    float rs0 = rsqrtf(q0 * (1.f / 256.f) - mu0 * mu0 + EPS);
    float mu1 = s1 * (1.f / 256.f);
    float rs1 = rsqrtf(q1 * (1.f / 256.f) - mu1 * mu1 + EPS);
    __half2* orow = g_xembh + ((long)b * 128 + c2) * 256;
#pragma unroll
    for (int i = 0; i < 8; i++) {
        int d = lane + i * 32;
        float o0 = (v0[i] - mu0) * rs0 * slw[d] + slb[d];
        float o1 = (v1[i] - mu1) * rs1 * slw[d] + slb[d];
        orow[d] = __floats2half2_rn(o0, o1);
    }
}

// ---------------- K2: x_prompt = [LN(embp)|prev] @ W^T + b + embp -----------
// LN fused; gmem tile loads register-double-buffered to hide LDG latency.
__global__ void xprompt_fused(const float* __restrict__ W,
                              const float* __restrict__ bias,
                              const float* __restrict__ embp,
                              const float* __restrict__ lnpw,
                              const float* __restrict__ lnpb,
                              const float* __restrict__ prev) {
    __shared__ float As[32][17];
    __shared__ float Ws[32][17];
    __shared__ float smu[32], srs[32];
    int tx = threadIdx.x, ty = threadIdx.y;
    int t = ty * 16 + tx;
    int p0 = blockIdx.y * 32;
    int d0 = blockIdx.x * 32;

    row_stats_32(embp, p0, smu, srs);
    __syncthreads();

    // per-thread tile coords (2 elements)
    int r0 = t >> 4, k0i = t & 15;          // i = 0
    int r1 = (256 + t) >> 4, k1i = t & 15;  // i = 1

    auto fetch = [&](int kt, float* v, float* w) {
        int kb = kt * 16;
        int gk0 = kb + k0i, gk1 = kb + k1i;
        v[0] = (gk0 < 256)
             ? (embp[(p0 + r0) * 256 + gk0] - smu[r0]) * srs[r0] * lnpw[gk0] + lnpb[gk0]
             : prev[(p0 + r0) * 256 + gk0 - 256];
        v[1] = (gk1 < 256)
             ? (embp[(p0 + r1) * 256 + gk1] - smu[r1]) * srs[r1] * lnpw[gk1] + lnpb[gk1]
             : prev[(p0 + r1) * 256 + gk1 - 256];
        w[0] = W[(d0 + r0) * 512 + gk0];
        w[1] = W[(d0 + r1) * 512 + gk1];
    };

    float va[2], wa[2], vb[2], wb[2];
    fetch(0, va, wa);

    float acc[2][2] = {{0.f, 0.f}, {0.f, 0.f}};
    for (int kt = 0; kt < 32; kt++) {
        As[r0][k0i] = va[0]; Ws[r0][k0i] = wa[0];
        As[r1][k1i] = va[1]; Ws[r1][k1i] = wa[1];
        __syncthreads();
        if (kt < 31) fetch(kt + 1, vb, wb);
#pragma unroll
        for (int kk = 0; kk < 16; kk++) {
            float a0 = As[ty * 2][kk], a1 = As[ty * 2 + 1][kk];
            float b0 = Ws[tx * 2][kk], b1 = Ws[tx * 2 + 1][kk];
            acc[0][0] += a0 * b0; acc[0][1] += a0 * b1;
            acc[1][0] += a1 * b0; acc[1][1] += a1 * b1;
        }
        __syncthreads();
        va[0] = vb[0]; va[1] = vb[1]; wa[0] = wb[0]; wa[1] = wb[1];
    }
#pragma unroll
    for (int i = 0; i < 2; i++)
#pragma unroll
        for (int j = 0; j < 2; j++) {
            int p = p0 + ty * 2 + i, dd = d0 + tx * 2 + j;
            g_xprompt[p * N256 + dd] = acc[i][j] + bias[dd] + embp[p * N256 + dd];
        }
}

// ---------------- K3: logits = x_prompt @ LN(embc)^T, softmax fused ----------
__global__ void logits_fused(const float* __restrict__ embc,
                             const float* __restrict__ lncw,
                             const float* __restrict__ lncb) {
    __shared__ float As[32][17];
    __shared__ float Bs[32][17];
    __shared__ float smu[32], srs[32];
    __shared__ int sflag;
    int tx = threadIdx.x, ty = threadIdx.y;
    int t = ty * 16 + tx;
    int p0 = blockIdx.y * 32;
    int c0 = blockIdx.x * 32;

    row_stats_32(embc, c0, smu, srs);
    __syncthreads();

    int r0 = t >> 4, k0i = t & 15;
    int r1 = (256 + t) >> 4, k1i = t & 15;

    auto fetch = [&](int kt, float* a, float* b) {
        int kb = kt * 16;
        int gk0 = kb + k0i, gk1 = kb + k1i;
        a[0] = g_xprompt[(p0 + r0) * N256 + gk0];
        a[1] = g_xprompt[(p0 + r1) * N256 + gk1];
        b[0] = (embc[(c0 + r0) * 256 + gk0] - smu[r0]) * srs[r0] * lncw[gk0] + lncb[gk0];
        b[1] = (embc[(c0 + r1) * 256 + gk1] - smu[r1]) * srs[r1] * lncw[gk1] + lncb[gk1];
    };

    float aa[2], ba[2], ab[2], bb[2];
    fetch(0, aa, ba);

    float acc[2][2] = {{0.f, 0.f}, {0.f, 0.f}};
    for (int kt = 0; kt < 16; kt++) {
        As[r0][k0i] = aa[0]; Bs[r0][k0i] = ba[0];
        As[r1][k1i] = aa[1]; Bs[r1][k1i] = ba[1];
        __syncthreads();
        if (kt < 15) fetch(kt + 1, ab, bb);
#pragma unroll
        for (int kk = 0; kk < 16; kk++) {
            float a0 = As[ty * 2][kk], a1 = As[ty * 2 + 1][kk];
            float b0 = Bs[tx * 2][kk], b1 = Bs[tx * 2 + 1][kk];
            acc[0][0] += a0 * b0; acc[0][1] += a0 * b1;
            acc[1][0] += a1 * b0; acc[1][1] += a1 * b1;
        }
        __syncthreads();
        aa[0] = ab[0]; aa[1] = ab[1]; ba[0] = bb[0]; ba[1] = bb[1];
    }
#pragma unroll
    for (int i = 0; i < 2; i++)
#pragma unroll
        for (int j = 0; j < 2; j++)
            g_logits[(p0 + ty * 2 + i) * N256 + c0 + tx * 2 + j] = acc[i][j];

    // arrival counting: 8 blocks per p-row group
    __threadfence();
    __syncthreads();
    if (t == 0) {
        int old = atomicAdd(&g_cnt[blockIdx.y], 1);
        sflag = (old == 7);
    }
    __syncthreads();
    if (!sflag) return;

    int lane = t & 31;
    int warp = t >> 5;
#pragma unroll
    for (int q = 0; q < 4; q++) {
        int p = p0 + warp * 4 + q;
        const float* row = g_logits + p * N256;
        float4 v0 = *(const float4*)(row + lane * 4);
        float4 v1 = *(const float4*)(row + 128 + lane * 4);
        float m = fmaxf(fmaxf(fmaxf(v0.x, v0.y), fmaxf(v0.z, v0.w)),
                        fmaxf(fmaxf(v1.x, v1.y), fmaxf(v1.z, v1.w)));
#pragma unroll
        for (int off = 16; off > 0; off >>= 1)
            m = fmaxf(m, __shfl_xor_sync(0xffffffff, m, off));
        float e0 = expf(v0.x - m), e1 = expf(v0.y - m);
        float e2 = expf(v0.z - m), e3 = expf(v0.w - m);
        float f0 = expf(v1.x - m), f1 = expf(v1.y - m);
        float f2 = expf(v1.z - m), f3 = expf(v1.w - m);
        float s = e0 + e1 + e2 + e3 + f0 + f1 + f2 + f3;
#pragma unroll
        for (int off = 16; off > 0; off >>= 1)
            s += __shfl_xor_sync(0xffffffff, s, off);
        float inv = 1.0f / s;
        __half2* mrow = g_maskh + p * 128;
        mrow[lane * 2 + 0] = __floats2half2_rn(e0 * inv, e1 * inv);
        mrow[lane * 2 + 1] = __floats2half2_rn(e2 * inv, e3 * inv);
        mrow[64 + lane * 2 + 0] = __floats2half2_rn(f0 * inv, f1 * inv);
        mrow[64 + lane * 2 + 1] = __floats2half2_rn(f2 * inv, f3 * inv);
    }
    if (t == 0) g_cnt[blockIdx.y] = 0;
}

// ---------------- K4: out[b] = mask @ xemb[b], fp16 mma, 4-stage pipeline ---
__device__ __forceinline__ void mma_f16(float c[4],
                                        uint32_t a0, uint32_t a1, uint32_t a2, uint32_t a3,
                                        uint32_t b0, uint32_t b1) {
    asm volatile(
        "mma.sync.aligned.m16n8k16.row.col.f32.f16.f16.f32 "
        "{%0,%1,%2,%3}, {%4,%5,%6,%7}, {%8,%9}, {%0,%1,%2,%3};"
        : "+f"(c[0]), "+f"(c[1]), "+f"(c[2]), "+f"(c[3])
        : "r"(a0), "r"(a1), "r"(a2), "r"(a3), "r"(b0), "r"(b1));
}

#define AS_STRIDE 20    // uint32: 16 + 4 pad
#define BS_STRIDE 136   // uint32: 128 + 8 pad
#define AS_BUF (128 * AS_STRIDE)
#define BS_BUF (16 * BS_STRIDE)
#define STAGE_U32 (AS_BUF + BS_BUF)
#define N_STAGES 4
#define GEMM_SMEM_BYTES (N_STAGES * STAGE_U32 * 4)   // 75776 B

__global__ __launch_bounds__(256, 2) void out_gemm_kernel(
    const float* __restrict__ ew,
    const float* __restrict__ eb,
    float* __restrict__ out) {
    extern __shared__ __align__(16) uint32_t smem[];

    int b = blockIdx.z;
    int m0 = blockIdx.y * 128;
    int n0 = blockIdx.x * 128;
    const uint32_t* A = (const uint32_t*)g_maskh;                     // [256][128]
    const uint32_t* B = (const uint32_t*)(g_xembh + (long)b * 32768); // [128][256]

    int tid = threadIdx.x;
    int lane = tid & 31;
    int warp = tid >> 5;
    int wm = (warp & 1) * 64;
    int wn = (warp >> 1) * 32;
    int grp = lane >> 2;
    int tig = lane & 3;

    int lrow = lane & 7;
    int lm = lane >> 3;
    int lds_row_off = lrow + ((lm & 1) << 3);
    int lds_col_off = (lm >> 1) << 2;

    float acc[4][4][4];
#pragma unroll
    for (int i = 0; i < 4; i++)
#pragma unroll
        for (int j = 0; j < 4; j++)
#pragma unroll
            for (int k = 0; k < 4; k++) acc[i][j][k] = 0.0f;

    auto load_tiles = [&](int stage, int kt) {
        uint32_t* As2 = smem + stage * STAGE_U32;
        uint32_t* Bs2 = As2 + AS_BUF;
        int kp0 = kt * 16;
#pragma unroll
        for (int t = 0; t < 2; t++) {
            int idx = t * 256 + tid;
            int r = idx >> 2;
            int kc = (idx & 3) << 2;
            cp_async16(&As2[r * AS_STRIDE + kc],
                       A + (m0 + r) * 128 + kp0 + kc);
        }
#pragma unroll
        for (int t = 0; t < 2; t++) {
            int idx = t * 256 + tid;
            int r = idx >> 5;
            int nc = (idx & 31) << 2;
            cp_async16(&Bs2[r * BS_STRIDE + nc],
                       B + (kp0 + r) * 256 + n0 + nc);
        }
        cp_commit();
    };

    load_tiles(0, 0);
    load_tiles(1, 1);
    load_tiles(2, 2);

#pragma unroll 4
    for (int kt = 0; kt < 8; kt++) {
        int stage = kt & 3;
        if (kt < 6)      { cp_wait<2>(); }
        else if (kt == 6){ cp_wait<1>(); }
        else             { cp_wait<0>(); }
        __syncthreads();
        if (kt + 3 < 8) load_tiles((kt + 3) & 3, kt + 3);

        const uint32_t* as = smem + stage * STAGE_U32;
        const uint32_t* bs = as + AS_BUF;
#pragma unroll
        for (int ks = 0; ks < 2; ks++) {
            int kk2 = ks * 8;
            uint32_t afr[4][4];
#pragma unroll
            for (int mi = 0; mi < 4; mi++) {
                int rb = wm + mi * 16 + lds_row_off;
                ldsm_x4(afr[mi][0], afr[mi][1], afr[mi][2], afr[mi][3],
                        &as[rb * AS_STRIDE + kk2 + lds_col_off]);
            }
            uint32_t bfr[4][2];
#pragma unroll
            for (int ni = 0; ni < 4; ni++) {
                int nb = wn + ni * 8 + grp;
                bfr[ni][0] = bs[(kk2 + tig) * BS_STRIDE + nb];
                bfr[ni][1] = bs[(kk2 + tig + 4) * BS_STRIDE + nb];
            }
#pragma unroll
            for (int mi = 0; mi < 4; mi++)
#pragma unroll
                for (int ni = 0; ni < 4; ni++)
                    mma_f16(acc[mi][ni],
                            afr[mi][0], afr[mi][1], afr[mi][2], afr[mi][3],
                            bfr[ni][0], bfr[ni][1]);
        }
    }

    // epilogue
    const __half2* maskb = g_maskh + b * 128;
    float ebb = eb[b];
#pragma unroll
    for (int mi = 0; mi < 4; mi++) {
#pragma unroll
        for (int h = 0; h < 2; h++) {
            int p = m0 + wm + mi * 16 + grp + h * 8;
            float scale = 1.0f + ew[p];
            __half2 mh = maskb[p >> 1];
            float mval = (p & 1) ? __high2float(mh) : __low2float(mh);
            float addv = mval * ebb;
            long rowoff = ((long)(b * 256 + p)) * 256;
#pragma unroll
            for (int ni = 0; ni < 4; ni++) {
                int d = n0 + wn + ni * 8 + tig * 2;
                float v0 = acc[mi][ni][h * 2 + 0] * scale + addv;
                float v1 = acc[mi][ni][h * 2 + 1] * scale + addv;
                *(float2*)(out + rowoff + d) = make_float2(v0, v1);
            }
        }
    }
}

// ---------------- launch -----------------------------------------------------
extern "C" void kernel_launch(void* const* d_in, const int* in_sizes, int n_in,
                              void* d_out, int out_size) {
    const float* x    = (const float*)d_in[0];
    const float* prev = (const float*)d_in[1];
    const float* few  = (const float*)d_in[2];
    const float* feb  = (const float*)d_in[3];
    const float* lnew = (const float*)d_in[4];
    const float* lneb = (const float*)d_in[5];
    const float* lncw = (const float*)d_in[6];
    const float* lncb = (const float*)d_in[7];
    const float* lnpw = (const float*)d_in[8];
    const float* lnpb = (const float*)d_in[9];
    const float* diw  = (const float*)d_in[10];
    const float* dib  = (const float*)d_in[11];
    const float* embc = (const float*)d_in[12];
    const float* embp = (const float*)d_in[13];
    const float* ew   = (const float*)d_in[14];
    const float* ebia = (const float*)d_in[15];
    float* out = (float*)d_out;

    static cudaStream_t s_chain;
    static cudaEvent_t ev_fork, ev_join;
    static bool init_done = false;
    if (!init_done) {
        cudaFuncSetAttribute(out_gemm_kernel,
                             cudaFuncAttributeMaxDynamicSharedMemorySize,
                             GEMM_SMEM_BYTES);
        cudaStreamCreateWithFlags(&s_chain, cudaStreamNonBlocking);
        cudaEventCreateWithFlags(&ev_fork, cudaEventDisableTiming);
        cudaEventCreateWithFlags(&ev_join, cudaEventDisableTiming);
        init_done = true;
    }

    // fork: chain on s_chain, xemb on origin stream
    cudaEventRecord(ev_fork, 0);
    cudaStreamWaitEvent(s_chain, ev_fork, 0);

    xprompt_fused<<<dim3(8, 8), dim3(16, 16), 0, s_chain>>>(diw, dib, embp,
                                                            lnpw, lnpb, prev);
    logits_fused<<<dim3(8, 8), dim3(16, 16), 0, s_chain>>>(embc, lncw, lncb);
    cudaEventRecord(ev_join, s_chain);

    xemb_kernel<<<4096, 256>>>(x, few, feb, lnew, lneb);

    // join: out_gemm needs both branches
    cudaStreamWaitEvent(0, ev_join, 0);
    out_gemm_kernel<<<dim3(2, 2, 256), 256, GEMM_SMEM_BYTES>>>(ew, ebia, out);
}

// round 13
// speedup vs baseline: 2.4123x; 1.0331x over previous
#include <cuda_runtime.h>
#include <cuda_fp16.h>
#include <cstdint>

// Problem constants: B=C=P=D=256
#define N256 256
#define EPS 1e-5f

// ---------------- scratch (device globals; no allocations allowed) ----------
__device__ __half2 g_xembh[256 * 128 * 256]; // [b][c/2][d] k-pair-packed halves
__device__ __half2 g_maskh[256 * 128];       // [p][c/2] k-pair-packed halves
__device__ float g_xprompt[256 * 256];       // [P,D]
__device__ float g_logits[256 * 256];        // [P,C]
__device__ int g_cnt[8];                     // arrival counters (zero-init, self-resetting)

// ---------------- helpers ----------------------------------------------------
__device__ __forceinline__ void cp_async16(void* smem, const void* gmem) {
    uint32_t s = (uint32_t)__cvta_generic_to_shared(smem);
    asm volatile("cp.async.cg.shared.global [%0], [%1], 16;" :: "r"(s), "l"(gmem));
}
__device__ __forceinline__ void cp_commit() {
    asm volatile("cp.async.commit_group;" ::: "memory");
}
template <int N>
__device__ __forceinline__ void cp_wait() {
    asm volatile("cp.async.wait_group %0;" :: "n"(N) : "memory");
}
__device__ __forceinline__ void ldsm_x4(uint32_t& r0, uint32_t& r1,
                                        uint32_t& r2, uint32_t& r3,
                                        const void* smem_ptr) {
    uint32_t a = (uint32_t)__cvta_generic_to_shared(smem_ptr);
    asm volatile("ldmatrix.sync.aligned.m8n8.x4.shared.b16 {%0,%1,%2,%3}, [%4];"
                 : "=r"(r0), "=r"(r1), "=r"(r2), "=r"(r3) : "r"(a));
}

// per-32-row LN stats: 8 threads per row, each reads 8 float4s.
__device__ __forceinline__ void row_stats_32(const float* __restrict__ src,
                                             int row0, float* smu, float* srs) {
    int t = threadIdx.y * blockDim.x + threadIdx.x;
    int r = t >> 3, j = t & 7;
    const float4* base4 = (const float4*)(src + (row0 + r) * 256);
    float s = 0.f, q = 0.f;
#pragma unroll
    for (int i = 0; i < 8; i++) {
        float4 v = base4[j + i * 8];
        s += v.x + v.y + v.z + v.w;
        q = fmaf(v.x, v.x, q); q = fmaf(v.y, v.y, q);
        q = fmaf(v.z, v.z, q); q = fmaf(v.w, v.w, q);
    }
#pragma unroll
    for (int off = 4; off > 0; off >>= 1) {
        s += __shfl_xor_sync(0xffffffffu, s, off, 8);
        q += __shfl_xor_sync(0xffffffffu, q, off, 8);
    }
    if (j == 0) {
        float mu = s * (1.f / 256.f);
        smu[r] = mu;
        srs[r] = rsqrtf(q * (1.f / 256.f) - mu * mu + EPS);
    }
}

// ---------------- K1: xemb pairs (grid 4096) ---------------------------------
__global__ void xemb_kernel(const float* __restrict__ x,
                            const float* __restrict__ few,
                            const float* __restrict__ feb,
                            const float* __restrict__ lnew,
                            const float* __restrict__ lneb) {
    __shared__ float sbuf[6 * 256];
    int tid = threadIdx.x;
    float* sw0 = sbuf;
    float* sb0 = sbuf + 256;
    float* sw1 = sbuf + 512;
    float* sb1 = sbuf + 768;
    float* slw = sbuf + 1024;
    float* slb = sbuf + 1280;
    int c2 = blockIdx.x >> 5;
    int bg = blockIdx.x & 31;
    int c0 = c2 * 2, c1 = c0 + 1;
    sw0[tid] = few[c0 * 256 + tid];
    sb0[tid] = feb[c0 * 256 + tid];
    sw1[tid] = few[c1 * 256 + tid];
    sb1[tid] = feb[c1 * 256 + tid];
    slw[tid] = lnew[tid];
    slb[tid] = lneb[tid];
    __syncthreads();

    int lane = tid & 31;
    int wid = tid >> 5;
    int b = bg * 8 + wid;
    float xv0 = x[b * 256 + c0];
    float xv1 = x[b * 256 + c1];
    float v0[8], v1[8];
    float s0 = 0.f, q0 = 0.f, s1 = 0.f, q1 = 0.f;
#pragma unroll
    for (int i = 0; i < 8; i++) {
        int d = lane + i * 32;
        float t0 = fmaf(xv0, sw0[d], sb0[d]);
        float t1 = fmaf(xv1, sw1[d], sb1[d]);
        t0 = t0 > 0.f ? t0 : 0.f;
        t1 = t1 > 0.f ? t1 : 0.f;
        v0[i] = t0; v1[i] = t1;
        s0 += t0; q0 = fmaf(t0, t0, q0);
        s1 += t1; q1 = fmaf(t1, t1, q1);
    }
#pragma unroll
    for (int off = 16; off > 0; off >>= 1) {
        s0 += __shfl_xor_sync(0xffffffff, s0, off);
        q0 += __shfl_xor_sync(0xffffffff, q0, off);
        s1 += __shfl_xor_sync(0xffffffff, s1, off);
        q1 += __shfl_xor_sync(0xffffffff, q1, off);
    }
    float mu0 = s0 * (1.f / 256.f);
    float rs0 = rsqrtf(q0 * (1.f / 256.f) - mu0 * mu0 + EPS);
    float mu1 = s1 * (1.f / 256.f);
    float rs1 = rsqrtf(q1 * (1.f / 256.f) - mu1 * mu1 + EPS);
    __half2* orow = g_xembh + ((long)b * 128 + c2) * 256;
#pragma unroll
    for (int i = 0; i < 8; i++) {
        int d = lane + i * 32;
        float o0 = (v0[i] - mu0) * rs0 * slw[d] + slb[d];
        float o1 = (v1[i] - mu1) * rs1 * slw[d] + slb[d];
        orow[d] = __floats2half2_rn(o0, o1);
    }
}

// ---------------- K2: x_prompt = [LN(embp)|prev] @ W^T + b + embp -----------
__global__ void xprompt_fused(const float* __restrict__ W,
                              const float* __restrict__ bias,
                              const float* __restrict__ embp,
                              const float* __restrict__ lnpw,
                              const float* __restrict__ lnpb,
                              const float* __restrict__ prev) {
    __shared__ float As[32][17];
    __shared__ float Ws[32][17];
    __shared__ float smu[32], srs[32];
    int tx = threadIdx.x, ty = threadIdx.y;
    int t = ty * 16 + tx;
    int p0 = blockIdx.y * 32;
    int d0 = blockIdx.x * 32;

    row_stats_32(embp, p0, smu, srs);
    __syncthreads();

    int r0 = t >> 4, k0i = t & 15;
    int r1 = (256 + t) >> 4, k1i = t & 15;

    auto fetch = [&](int kt, float* v, float* w) {
        int kb = kt * 16;
        int gk0 = kb + k0i, gk1 = kb + k1i;
        v[0] = (gk0 < 256)
             ? (embp[(p0 + r0) * 256 + gk0] - smu[r0]) * srs[r0] * lnpw[gk0] + lnpb[gk0]
             : prev[(p0 + r0) * 256 + gk0 - 256];
        v[1] = (gk1 < 256)
             ? (embp[(p0 + r1) * 256 + gk1] - smu[r1]) * srs[r1] * lnpw[gk1] + lnpb[gk1]
             : prev[(p0 + r1) * 256 + gk1 - 256];
        w[0] = W[(d0 + r0) * 512 + gk0];
        w[1] = W[(d0 + r1) * 512 + gk1];
    };

    float va[2], wa[2], vb[2], wb[2];
    fetch(0, va, wa);

    float acc[2][2] = {{0.f, 0.f}, {0.f, 0.f}};
    for (int kt = 0; kt < 32; kt++) {
        As[r0][k0i] = va[0]; Ws[r0][k0i] = wa[0];
        As[r1][k1i] = va[1]; Ws[r1][k1i] = wa[1];
        __syncthreads();
        if (kt < 31) fetch(kt + 1, vb, wb);
#pragma unroll
        for (int kk = 0; kk < 16; kk++) {
            float a0 = As[ty * 2][kk], a1 = As[ty * 2 + 1][kk];
            float b0 = Ws[tx * 2][kk], b1 = Ws[tx * 2 + 1][kk];
            acc[0][0] += a0 * b0; acc[0][1] += a0 * b1;
            acc[1][0] += a1 * b0; acc[1][1] += a1 * b1;
        }
        __syncthreads();
        va[0] = vb[0]; va[1] = vb[1]; wa[0] = wb[0]; wa[1] = wb[1];
    }
#pragma unroll
    for (int i = 0; i < 2; i++)
#pragma unroll
        for (int j = 0; j < 2; j++) {
            int p = p0 + ty * 2 + i, dd = d0 + tx * 2 + j;
            g_xprompt[p * N256 + dd] = acc[i][j] + bias[dd] + embp[p * N256 + dd];
        }
}

// ---------------- K3: logits = x_prompt @ LN(embc)^T, softmax fused ----------
__global__ void logits_fused(const float* __restrict__ embc,
                             const float* __restrict__ lncw,
                             const float* __restrict__ lncb) {
    __shared__ float As[32][17];
    __shared__ float Bs[32][17];
    __shared__ float smu[32], srs[32];
    __shared__ int sflag;
    int tx = threadIdx.x, ty = threadIdx.y;
    int t = ty * 16 + tx;
    int p0 = blockIdx.y * 32;
    int c0 = blockIdx.x * 32;

    row_stats_32(embc, c0, smu, srs);
    __syncthreads();

    int r0 = t >> 4, k0i = t & 15;
    int r1 = (256 + t) >> 4, k1i = t & 15;

    auto fetch = [&](int kt, float* a, float* b) {
        int kb = kt * 16;
        int gk0 = kb + k0i, gk1 = kb + k1i;
        a[0] = g_xprompt[(p0 + r0) * N256 + gk0];
        a[1] = g_xprompt[(p0 + r1) * N256 + gk1];
        b[0] = (embc[(c0 + r0) * 256 + gk0] - smu[r0]) * srs[r0] * lncw[gk0] + lncb[gk0];
        b[1] = (embc[(c0 + r1) * 256 + gk1] - smu[r1]) * srs[r1] * lncw[gk1] + lncb[gk1];
    };

    float aa[2], ba[2], ab[2], bb[2];
    fetch(0, aa, ba);

    float acc[2][2] = {{0.f, 0.f}, {0.f, 0.f}};
    for (int kt = 0; kt < 16; kt++) {
        As[r0][k0i] = aa[0]; Bs[r0][k0i] = ba[0];
        As[r1][k1i] = aa[1]; Bs[r1][k1i] = ba[1];
        __syncthreads();
        if (kt < 15) fetch(kt + 1, ab, bb);
#pragma unroll
        for (int kk = 0; kk < 16; kk++) {
            float a0 = As[ty * 2][kk], a1 = As[ty * 2 + 1][kk];
            float b0 = Bs[tx * 2][kk], b1 = Bs[tx * 2 + 1][kk];
            acc[0][0] += a0 * b0; acc[0][1] += a0 * b1;
            acc[1][0] += a1 * b0; acc[1][1] += a1 * b1;
        }
        __syncthreads();
        aa[0] = ab[0]; aa[1] = ab[1]; ba[0] = bb[0]; ba[1] = bb[1];
    }
#pragma unroll
    for (int i = 0; i < 2; i++)
#pragma unroll
        for (int j = 0; j < 2; j++)
            g_logits[(p0 + ty * 2 + i) * N256 + c0 + tx * 2 + j] = acc[i][j];

    __threadfence();
    __syncthreads();
    if (t == 0) {
        int old = atomicAdd(&g_cnt[blockIdx.y], 1);
        sflag = (old == 7);
    }
    __syncthreads();
    if (!sflag) return;

    int lane = t & 31;
    int warp = t >> 5;
#pragma unroll
    for (int q = 0; q < 4; q++) {
        int p = p0 + warp * 4 + q;
        const float* row = g_logits + p * N256;
        float4 v0 = *(const float4*)(row + lane * 4);
        float4 v1 = *(const float4*)(row + 128 + lane * 4);
        float m = fmaxf(fmaxf(fmaxf(v0.x, v0.y), fmaxf(v0.z, v0.w)),
                        fmaxf(fmaxf(v1.x, v1.y), fmaxf(v1.z, v1.w)));
#pragma unroll
        for (int off = 16; off > 0; off >>= 1)
            m = fmaxf(m, __shfl_xor_sync(0xffffffff, m, off));
        float e0 = expf(v0.x - m), e1 = expf(v0.y - m);
        float e2 = expf(v0.z - m), e3 = expf(v0.w - m);
        float f0 = expf(v1.x - m), f1 = expf(v1.y - m);
        float f2 = expf(v1.z - m), f3 = expf(v1.w - m);
        float s = e0 + e1 + e2 + e3 + f0 + f1 + f2 + f3;
#pragma unroll
        for (int off = 16; off > 0; off >>= 1)
            s += __shfl_xor_sync(0xffffffff, s, off);
        float inv = 1.0f / s;
        __half2* mrow = g_maskh + p * 128;
        mrow[lane * 2 + 0] = __floats2half2_rn(e0 * inv, e1 * inv);
        mrow[lane * 2 + 1] = __floats2half2_rn(e2 * inv, e3 * inv);
        mrow[64 + lane * 2 + 0] = __floats2half2_rn(f0 * inv, f1 * inv);
        mrow[64 + lane * 2 + 1] = __floats2half2_rn(f2 * inv, f3 * inv);
    }
    if (t == 0) g_cnt[blockIdx.y] = 0;
}

// ---------------- K4: out[b] = mask @ xemb[b], fp16 mma ---------------------
// K-chunk 64 halves (32 u32), 4 iterations, 3 stages, 4 barriers total.
__device__ __forceinline__ void mma_f16(float c[4],
                                        uint32_t a0, uint32_t a1, uint32_t a2, uint32_t a3,
                                        uint32_t b0, uint32_t b1) {
    asm volatile(
        "mma.sync.aligned.m16n8k16.row.col.f32.f16.f16.f32 "
        "{%0,%1,%2,%3}, {%4,%5,%6,%7}, {%8,%9}, {%0,%1,%2,%3};"
        : "+f"(c[0]), "+f"(c[1]), "+f"(c[2]), "+f"(c[3])
        : "r"(a0), "r"(a1), "r"(a2), "r"(a3), "r"(b0), "r"(b1));
}

#define AS_STRIDE 36    // uint32: 32 + 4 pad (ldmatrix rows: 4r mod 32 distinct)
#define BS_STRIDE 136   // uint32: 128 + 8 pad
#define AS_BUF (128 * AS_STRIDE)   // 4608 u32
#define BS_BUF (32 * BS_STRIDE)    // 4352 u32
#define STAGE_U32 (AS_BUF + BS_BUF)
#define N_STAGES 3
#define GEMM_SMEM_BYTES (N_STAGES * STAGE_U32 * 4)   // 107520 B

__global__ __launch_bounds__(256, 2) void out_gemm_kernel(
    const float* __restrict__ ew,
    const float* __restrict__ eb,
    float* __restrict__ out) {
    extern __shared__ __align__(16) uint32_t smem[];

    int b = blockIdx.z;
    int m0 = blockIdx.y * 128;
    int n0 = blockIdx.x * 128;
    const uint32_t* A = (const uint32_t*)g_maskh;                     // [256][128]
    const uint32_t* B = (const uint32_t*)(g_xembh + (long)b * 32768); // [128][256]

    int tid = threadIdx.x;
    int lane = tid & 31;
    int warp = tid >> 5;
    int wm = (warp & 1) * 64;
    int wn = (warp >> 1) * 32;
    int grp = lane >> 2;
    int tig = lane & 3;

    int lrow = lane & 7;
    int lm = lane >> 3;
    int lds_row_off = lrow + ((lm & 1) << 3);
    int lds_col_off = (lm >> 1) << 2;

    float acc[4][4][4];
#pragma unroll
    for (int i = 0; i < 4; i++)
#pragma unroll
        for (int j = 0; j < 4; j++)
#pragma unroll
            for (int k = 0; k < 4; k++) acc[i][j][k] = 0.0f;

    // chunk kt covers u32-cols kp0 = kt*32 .. +31 (k halves kt*64 .. +63)
    auto load_tiles = [&](int stage, int kt) {
        uint32_t* As2 = smem + stage * STAGE_U32;
        uint32_t* Bs2 = As2 + AS_BUF;
        int kp0 = kt * 32;
        // A: 128 rows x 32 u32 = 1024 float4 -> 4/thread
#pragma unroll
        for (int t = 0; t < 4; t++) {
            int idx = t * 256 + tid;
            int r = idx >> 3;
            int kc = (idx & 7) << 2;
            cp_async16(&As2[r * AS_STRIDE + kc],
                       A + (m0 + r) * 128 + kp0 + kc);
        }
        // B: 32 rows x 128 u32 = 1024 float4 -> 4/thread
#pragma unroll
        for (int t = 0; t < 4; t++) {
            int idx = t * 256 + tid;
            int r = idx >> 5;
            int nc = (idx & 31) << 2;
            cp_async16(&Bs2[r * BS_STRIDE + nc],
                       B + (kp0 + r) * 256 + n0 + nc);
        }
        cp_commit();
    };

    load_tiles(0, 0);
    load_tiles(1, 1);
    load_tiles(2, 2);

#pragma unroll
    for (int kt = 0; kt < 4; kt++) {
        if (kt == 0)      { cp_wait<2>(); }
        else if (kt < 3)  { cp_wait<1>(); }
        else              { cp_wait<0>(); }
        __syncthreads();
        if (kt == 1) load_tiles(0, 3);   // stage 0 free: all warps past kt=0

        int stage = kt % 3;
        const uint32_t* as = smem + stage * STAGE_U32;
        const uint32_t* bs = as + AS_BUF;
#pragma unroll
        for (int ks = 0; ks < 4; ks++) {
            int kk2 = ks * 8;
            uint32_t afr[4][4];
#pragma unroll
            for (int mi = 0; mi < 4; mi++) {
                int rb = wm + mi * 16 + lds_row_off;
                ldsm_x4(afr[mi][0], afr[mi][1], afr[mi][2], afr[mi][3],
                        &as[rb * AS_STRIDE + kk2 + lds_col_off]);
            }
            uint32_t bfr[4][2];
#pragma unroll
            for (int ni = 0; ni < 4; ni++) {
                int nb = wn + ni * 8 + grp;
                bfr[ni][0] = bs[(kk2 + tig) * BS_STRIDE + nb];
                bfr[ni][1] = bs[(kk2 + tig + 4) * BS_STRIDE + nb];
            }
#pragma unroll
            for (int mi = 0; mi < 4; mi++)
#pragma unroll
                for (int ni = 0; ni < 4; ni++)
                    mma_f16(acc[mi][ni],
                            afr[mi][0], afr[mi][1], afr[mi][2], afr[mi][3],
                            bfr[ni][0], bfr[ni][1]);
        }
    }

    // epilogue
    const __half2* maskb = g_maskh + b * 128;
    float ebb = eb[b];
#pragma unroll
    for (int mi = 0; mi < 4; mi++) {
#pragma unroll
        for (int h = 0; h < 2; h++) {
            int p = m0 + wm + mi * 16 + grp + h * 8;
            float scale = 1.0f + ew[p];
            __half2 mh = maskb[p >> 1];
            float mval = (p & 1) ? __high2float(mh) : __low2float(mh);
            float addv = mval * ebb;
            long rowoff = ((long)(b * 256 + p)) * 256;
#pragma unroll
            for (int ni = 0; ni < 4; ni++) {
                int d = n0 + wn + ni * 8 + tig * 2;
                float v0 = acc[mi][ni][h * 2 + 0] * scale + addv;
                float v1 = acc[mi][ni][h * 2 + 1] * scale + addv;
                *(float2*)(out + rowoff + d) = make_float2(v0, v1);
            }
        }
    }
}

// ---------------- launch -----------------------------------------------------
extern "C" void kernel_launch(void* const* d_in, const int* in_sizes, int n_in,
                              void* d_out, int out_size) {
    const float* x    = (const float*)d_in[0];
    const float* prev = (const float*)d_in[1];
    const float* few  = (const float*)d_in[2];
    const float* feb  = (const float*)d_in[3];
    const float* lnew = (const float*)d_in[4];
    const float* lneb = (const float*)d_in[5];
    const float* lncw = (const float*)d_in[6];
    const float* lncb = (const float*)d_in[7];
    const float* lnpw = (const float*)d_in[8];
    const float* lnpb = (const float*)d_in[9];
    const float* diw  = (const float*)d_in[10];
    const float* dib  = (const float*)d_in[11];
    const float* embc = (const float*)d_in[12];
    const float* embp = (const float*)d_in[13];
    const float* ew   = (const float*)d_in[14];
    const float* ebia = (const float*)d_in[15];
    float* out = (float*)d_out;

    static cudaStream_t s_chain;
    static cudaEvent_t ev_fork, ev_join;
    static bool init_done = false;
    if (!init_done) {
        cudaFuncSetAttribute(out_gemm_kernel,
                             cudaFuncAttributeMaxDynamicSharedMemorySize,
                             GEMM_SMEM_BYTES);
        cudaStreamCreateWithFlags(&s_chain, cudaStreamNonBlocking);
        cudaEventCreateWithFlags(&ev_fork, cudaEventDisableTiming);
        cudaEventCreateWithFlags(&ev_join, cudaEventDisableTiming);
        init_done = true;
    }

    cudaEventRecord(ev_fork, 0);
    cudaStreamWaitEvent(s_chain, ev_fork, 0);

    xprompt_fused<<<dim3(8, 8), dim3(16, 16), 0, s_chain>>>(diw, dib, embp,
                                                            lnpw, lnpb, prev);
    logits_fused<<<dim3(8, 8), dim3(16, 16), 0, s_chain>>>(embc, lncw, lncb);
    cudaEventRecord(ev_join, s_chain);

    xemb_kernel<<<4096, 256>>>(x, few, feb, lnew, lneb);

    cudaStreamWaitEvent(0, ev_join, 0);
    out_gemm_kernel<<<dim3(2, 2, 256), 256, GEMM_SMEM_BYTES>>>(ew, ebia, out);
}